// round 2
// baseline (speedup 1.0000x reference)
#include <cuda_runtime.h>

// ---------------------------------------------------------------------------
// CondTransportKernel: fused GP conditional-transport map.
//   Inputs (d_in order):
//     0 x_mu        [8192,32] f32
//     1 y_eta       [8192,32] f32
//     2 y_mean      [8192,32] f32
//     3 y_var       [8192,32] f32
//     4 X_mean      [8192,64] f32
//     5 X_var       [8192,96] f32
//     6 Z_mean      [8192,32] f32
//     7 Z_var       [8192,32] f32
//     8 kXXmean_inv [8192,8192] f32
//     9 kXXvar_inv  [8192,8192] f32
//   out [8192,32] f32 = y_mean + y_var + z_mean + z_var
// ---------------------------------------------------------------------------

#define N 8192

// -------------------- device scratch (static, no allocations) --------------
__device__ float g_xqm[N * 64];   // query features, mean map  [x_mu | y_mean+y_var]
__device__ float g_xqv[N * 96];   // query features, var  map  [x_mu | .01*flip(y_eta) | y_mean+y_var]
__device__ float g_qnm[N];        // |q|^2 for mean map
__device__ float g_qnv[N];        // |q|^2 for var map
__device__ float g_Xnm[N];        // |X_mean row|^2
__device__ float g_Xnv[N];        // |X_var  row|^2
__device__ float g_Lm[N * 32];    // Lambda_mean
__device__ float g_Lv[N * 32];    // Lambda_var
__device__ float g_zm[N * 32];    // z_mean
__device__ float g_zv[N * 32];    // z_var

// -------------------- prep: build query features + norms -------------------
// One warp per query row q. lane = column (DX=DY=32).
__global__ void prep_q_kernel(const float* __restrict__ x_mu,
                              const float* __restrict__ y_eta,
                              const float* __restrict__ y_mean,
                              const float* __restrict__ y_var) {
    int warp = (blockIdx.x * blockDim.x + threadIdx.x) >> 5;
    int lane = threadIdx.x & 31;
    if (warp >= N) return;
    int q = warp;
    float a = x_mu[q * 32 + lane];
    float m = y_mean[q * 32 + lane] + y_var[q * 32 + lane];
    float e = 0.01f * y_eta[(N - 1 - q) * 32 + lane];

    g_xqm[q * 64 + lane]      = a;
    g_xqm[q * 64 + 32 + lane] = m;
    g_xqv[q * 96 + lane]      = a;
    g_xqv[q * 96 + 32 + lane] = e;
    g_xqv[q * 96 + 64 + lane] = m;

    float nm = a * a + m * m;
    float nv = nm + e * e;
    #pragma unroll
    for (int off = 16; off; off >>= 1) {
        nm += __shfl_xor_sync(0xffffffffu, nm, off);
        nv += __shfl_xor_sync(0xffffffffu, nv, off);
    }
    if (lane == 0) { g_qnm[q] = nm; g_qnv[q] = nv; }
}

// One warp per X row: squared norms of X_mean (64 cols) and X_var (96 cols).
__global__ void prep_X_kernel(const float* __restrict__ Xm,
                              const float* __restrict__ Xv) {
    int warp = (blockIdx.x * blockDim.x + threadIdx.x) >> 5;
    int lane = threadIdx.x & 31;
    if (warp >= N) return;
    int i = warp;
    float nm = 0.f;
    #pragma unroll
    for (int c = 0; c < 64; c += 32) {
        float v = Xm[(size_t)i * 64 + c + lane];
        nm += v * v;
    }
    float nv = 0.f;
    #pragma unroll
    for (int c = 0; c < 96; c += 32) {
        float v = Xv[(size_t)i * 96 + c + lane];
        nv += v * v;
    }
    #pragma unroll
    for (int off = 16; off; off >>= 1) {
        nm += __shfl_xor_sync(0xffffffffu, nm, off);
        nv += __shfl_xor_sync(0xffffffffu, nv, off);
    }
    if (lane == 0) { g_Xnm[i] = nm; g_Xnv[i] = nv; }
}

// -------------------- Lambda = kXX_inv @ Z  (M=8192, N=32, K=8192) ----------
// Block: 64 rows x 32 cols. 256 threads; warp w owns rows w*8..w*8+7, lane = col.
__global__ __launch_bounds__(256) void lambda_gemm_kernel(
    const float* __restrict__ A0, const float* __restrict__ Z0,
    const float* __restrict__ A1, const float* __restrict__ Z1) {
    const float* A = blockIdx.y ? A1 : A0;
    const float* Z = blockIdx.y ? Z1 : Z0;
    float* L       = blockIdx.y ? g_Lv : g_Lm;

    __shared__ __align__(16) float sA[64 * 68];   // 64 rows x (64 k + pad4)
    __shared__ __align__(16) float sZ[64 * 36];   // 64 k   x (32 col + pad4)

    const int tid  = threadIdx.x;
    const int col  = tid & 31;
    const int rowg = tid >> 5;            // warp id 0..7
    const int rb   = blockIdx.x * 64;

    float acc[8];
    #pragma unroll
    for (int r = 0; r < 8; r++) acc[r] = 0.f;

    for (int k0 = 0; k0 < N; k0 += 64) {
        // load A tile: 64 rows x 64 cols = 1024 float4, 4 per thread
        {
            int idx = tid;
            #pragma unroll
            for (int it = 0; it < 4; it++, idx += 256) {
                int r = idx >> 4, v = idx & 15;
                float4 av = *(const float4*)&A[(size_t)(rb + r) * N + k0 + v * 4];
                *(float4*)&sA[r * 68 + v * 4] = av;
            }
        }
        // load Z tile: 64 k x 32 cols = 512 float4, 2 per thread
        {
            int idx = tid;
            #pragma unroll
            for (int it = 0; it < 2; it++, idx += 256) {
                int r = idx >> 3, v = idx & 7;
                float4 zv = *(const float4*)&Z[(size_t)(k0 + r) * 32 + v * 4];
                *(float4*)&sZ[r * 36 + v * 4] = zv;
            }
        }
        __syncthreads();

        #pragma unroll
        for (int k = 0; k < 64; k += 4) {
            float4 a4[8];
            #pragma unroll
            for (int r = 0; r < 8; r++)
                a4[r] = *(const float4*)&sA[(rowg * 8 + r) * 68 + k];   // broadcast
            #pragma unroll
            for (int kk = 0; kk < 4; kk++) {
                float zv = sZ[(k + kk) * 36 + col];
                #pragma unroll
                for (int r = 0; r < 8; r++)
                    acc[r] += (&a4[r].x)[kk] * zv;
            }
        }
        __syncthreads();
    }

    #pragma unroll
    for (int r = 0; r < 8; r++)
        L[(size_t)(rb + rowg * 8 + r) * 32 + col] = acc[r];
}

// -------------------- fused z = rbf(X, q).T @ Lambda ------------------------
// Block: 32 queries x all 8192 X, streamed in chunks of 64.
// Thread mapping: qg = tid>>3 (query row 0..31), xg = tid&7 (x sub-group).
// Thread owns x rows {xg, xg+8, ..., xg+56} of each chunk; acc[32] in regs.
// Final: shuffle-reduce over the 8 xg lanes (lane bits 0..2).
__global__ __launch_bounds__(256) void fused_rbf_kernel(
    const float* __restrict__ Xm, const float* __restrict__ Xv) {
    __shared__ __align__(16) float sQ[32 * 100];
    __shared__ __align__(16) float sX[64 * 100];
    __shared__ __align__(16) float sL[64 * 36];
    __shared__ float sXn[64];

    const int task = blockIdx.y;
    const float* Xg = task ? Xv    : Xm;
    const float* Qg = task ? g_xqv : g_xqm;
    const float* Lg = task ? g_Lv  : g_Lm;
    const float* Xn = task ? g_Xnv : g_Xnm;
    const float* Qn = task ? g_qnv : g_qnm;
    float* Zg       = task ? g_zv  : g_zm;
    const int D  = task ? 96 : 64;
    const int SD = D + 4;                      // 68 / 100: stride ≡ 4 (mod 32) banks

    const int tid  = threadIdx.x;
    const int lane = tid & 31;
    const int warp = tid >> 5;
    const int qg   = tid >> 3;                 // 0..31
    const int xg   = tid & 7;                  // 0..7
    const int qb   = blockIdx.x * 32;

    // load Q tile once
    for (int r = warp; r < 32; r += 8)
        for (int c = lane; c < D; c += 32)
            sQ[r * SD + c] = Qg[(size_t)(qb + r) * D + c];

    const float qn = Qn[qb + qg];

    float acc[32];
    #pragma unroll
    for (int c = 0; c < 32; c++) acc[c] = 0.f;

    for (int xb = 0; xb < N; xb += 64) {
        for (int r = warp; r < 64; r += 8) {
            for (int c = lane; c < D; c += 32)
                sX[r * SD + c] = Xg[(size_t)(xb + r) * D + c];
            sL[r * 36 + lane] = Lg[(size_t)(xb + r) * 32 + lane];
        }
        if (tid < 64) sXn[tid] = Xn[xb + tid];
        __syncthreads();

        // dot products q . x for 8 x-rows
        float dot[8];
        #pragma unroll
        for (int i = 0; i < 8; i++) dot[i] = 0.f;

        const float* qp = &sQ[qg * SD];
        for (int k = 0; k < D; k += 4) {
            float4 q4 = *(const float4*)&qp[k];
            #pragma unroll
            for (int i = 0; i < 8; i++) {
                float4 x4 = *(const float4*)&sX[(xg + 8 * i) * SD + k];
                dot[i] += q4.x * x4.x + q4.y * x4.y + q4.z * x4.z + q4.w * x4.w;
            }
        }

        // p = exp(-max(d2,0)/(2*l^2)), l=8 -> /128
        float p[8];
        #pragma unroll
        for (int i = 0; i < 8; i++) {
            float d2 = fmaxf(qn + sXn[xg + 8 * i] - 2.f * dot[i], 0.f);
            p[i] = __expf(-0.0078125f * d2);
        }

        // acc += P @ Lambda  (width 32)
        #pragma unroll
        for (int i = 0; i < 8; i++) {
            const float* lp = &sL[(xg + 8 * i) * 36];
            #pragma unroll
            for (int c4 = 0; c4 < 32; c4 += 4) {
                float4 l4 = *(const float4*)&lp[c4];
                acc[c4 + 0] += p[i] * l4.x;
                acc[c4 + 1] += p[i] * l4.y;
                acc[c4 + 2] += p[i] * l4.z;
                acc[c4 + 3] += p[i] * l4.w;
            }
        }
        __syncthreads();
    }

    // reduce over the 8 xg lanes (lane bits 0..2)
    #pragma unroll
    for (int c = 0; c < 32; c++) {
        acc[c] += __shfl_xor_sync(0xffffffffu, acc[c], 1);
        acc[c] += __shfl_xor_sync(0xffffffffu, acc[c], 2);
        acc[c] += __shfl_xor_sync(0xffffffffu, acc[c], 4);
    }
    if (xg == 0) {
        float* zrow = &Zg[(size_t)(qb + qg) * 32];
        #pragma unroll
        for (int c4 = 0; c4 < 32; c4 += 4) {
            float4 v = make_float4(acc[c4], acc[c4 + 1], acc[c4 + 2], acc[c4 + 3]);
            *(float4*)&zrow[c4] = v;
        }
    }
}

// -------------------- combine ----------------------------------------------
__global__ void combine_kernel(const float* __restrict__ y_mean,
                               const float* __restrict__ y_var,
                               float* __restrict__ out) {
    int i = blockIdx.x * blockDim.x + threadIdx.x;
    if (i < N * 32)
        out[i] = (y_mean[i] + g_zm[i]) + (y_var[i] + g_zv[i]);
}

// -------------------- launch ------------------------------------------------
extern "C" void kernel_launch(void* const* d_in, const int* in_sizes, int n_in,
                              void* d_out, int out_size) {
    const float* x_mu   = (const float*)d_in[0];
    const float* y_eta  = (const float*)d_in[1];
    const float* y_mean = (const float*)d_in[2];
    const float* y_var  = (const float*)d_in[3];
    const float* X_mean = (const float*)d_in[4];
    const float* X_var  = (const float*)d_in[5];
    const float* Z_mean = (const float*)d_in[6];
    const float* Z_var  = (const float*)d_in[7];
    const float* kMi    = (const float*)d_in[8];
    const float* kVi    = (const float*)d_in[9];
    float* out = (float*)d_out;

    prep_q_kernel<<<(N * 32 + 255) / 256, 256>>>(x_mu, y_eta, y_mean, y_var);
    prep_X_kernel<<<(N * 32 + 255) / 256, 256>>>(X_mean, X_var);

    lambda_gemm_kernel<<<dim3(N / 64, 2), 256>>>(kMi, Z_mean, kVi, Z_var);

    fused_rbf_kernel<<<dim3(N / 32, 2), 256>>>(X_mean, X_var);

    combine_kernel<<<(N * 32 + 255) / 256, 256>>>(y_mean, y_var, out);
}

// round 3
// speedup vs baseline: 2.4212x; 2.4212x over previous
#include <cuda_runtime.h>

// ---------------------------------------------------------------------------
// CondTransportKernel: fused GP conditional-transport map.
//   out [8192,32] f32 = y_mean + y_var + z_mean + z_var
//   z_* = rbf(X_*, q_*).T @ (kXX*_inv @ Z_*)
// ---------------------------------------------------------------------------

#define N 8192

// -------------------- device scratch (static, no allocations) --------------
__device__ float g_xqm[N * 64];   // query features, mean map  [x_mu | y_mean+y_var]
__device__ float g_xqv[N * 96];   // query features, var  map  [x_mu | .01*flip(y_eta) | y_mean+y_var]
__device__ float g_qnm[N];        // |q|^2 mean map
__device__ float g_qnv[N];        // |q|^2 var map
__device__ float g_Xnm[N];        // |X_mean row|^2
__device__ float g_Xnv[N];        // |X_var  row|^2
__device__ float g_Lm[N * 32];    // Lambda_mean
__device__ float g_Lv[N * 32];    // Lambda_var
__device__ float g_zm[N * 32];    // z_mean
__device__ float g_zv[N * 32];    // z_var

// -------------------- prep: build query features + norms -------------------
__global__ void prep_q_kernel(const float* __restrict__ x_mu,
                              const float* __restrict__ y_eta,
                              const float* __restrict__ y_mean,
                              const float* __restrict__ y_var) {
    int warp = (blockIdx.x * blockDim.x + threadIdx.x) >> 5;
    int lane = threadIdx.x & 31;
    if (warp >= N) return;
    int q = warp;
    float a = x_mu[q * 32 + lane];
    float m = y_mean[q * 32 + lane] + y_var[q * 32 + lane];
    float e = 0.01f * y_eta[(N - 1 - q) * 32 + lane];

    g_xqm[q * 64 + lane]      = a;
    g_xqm[q * 64 + 32 + lane] = m;
    g_xqv[q * 96 + lane]      = a;
    g_xqv[q * 96 + 32 + lane] = e;
    g_xqv[q * 96 + 64 + lane] = m;

    float nm = a * a + m * m;
    float nv = nm + e * e;
    #pragma unroll
    for (int off = 16; off; off >>= 1) {
        nm += __shfl_xor_sync(0xffffffffu, nm, off);
        nv += __shfl_xor_sync(0xffffffffu, nv, off);
    }
    if (lane == 0) { g_qnm[q] = nm; g_qnv[q] = nv; }
}

__global__ void prep_X_kernel(const float* __restrict__ Xm,
                              const float* __restrict__ Xv) {
    int warp = (blockIdx.x * blockDim.x + threadIdx.x) >> 5;
    int lane = threadIdx.x & 31;
    if (warp >= N) return;
    int i = warp;
    float nm = 0.f;
    #pragma unroll
    for (int c = 0; c < 64; c += 32) {
        float v = Xm[(size_t)i * 64 + c + lane];
        nm += v * v;
    }
    float nv = 0.f;
    #pragma unroll
    for (int c = 0; c < 96; c += 32) {
        float v = Xv[(size_t)i * 96 + c + lane];
        nv += v * v;
    }
    #pragma unroll
    for (int off = 16; off; off >>= 1) {
        nm += __shfl_xor_sync(0xffffffffu, nm, off);
        nv += __shfl_xor_sync(0xffffffffu, nv, off);
    }
    if (lane == 0) { g_Xnm[i] = nm; g_Xnv[i] = nv; }
}

// -------------------- Lambda = kXX_inv @ Z  (M=8192, N=32, K=8192) ----------
__global__ __launch_bounds__(256) void lambda_gemm_kernel(
    const float* __restrict__ A0, const float* __restrict__ Z0,
    const float* __restrict__ A1, const float* __restrict__ Z1) {
    const float* A = blockIdx.y ? A1 : A0;
    const float* Z = blockIdx.y ? Z1 : Z0;
    float* L       = blockIdx.y ? g_Lv : g_Lm;

    __shared__ __align__(16) float sA[64 * 68];
    __shared__ __align__(16) float sZ[64 * 36];

    const int tid  = threadIdx.x;
    const int col  = tid & 31;
    const int rowg = tid >> 5;
    const int rb   = blockIdx.x * 64;

    float acc[8];
    #pragma unroll
    for (int r = 0; r < 8; r++) acc[r] = 0.f;

    for (int k0 = 0; k0 < N; k0 += 64) {
        {
            int idx = tid;
            #pragma unroll
            for (int it = 0; it < 4; it++, idx += 256) {
                int r = idx >> 4, v = idx & 15;
                float4 av = *(const float4*)&A[(size_t)(rb + r) * N + k0 + v * 4];
                *(float4*)&sA[r * 68 + v * 4] = av;
            }
        }
        {
            int idx = tid;
            #pragma unroll
            for (int it = 0; it < 2; it++, idx += 256) {
                int r = idx >> 3, v = idx & 7;
                float4 zv = *(const float4*)&Z[(size_t)(k0 + r) * 32 + v * 4];
                *(float4*)&sZ[r * 36 + v * 4] = zv;
            }
        }
        __syncthreads();

        #pragma unroll
        for (int k = 0; k < 64; k += 4) {
            float4 a4[8];
            #pragma unroll
            for (int r = 0; r < 8; r++)
                a4[r] = *(const float4*)&sA[(rowg * 8 + r) * 68 + k];
            #pragma unroll
            for (int kk = 0; kk < 4; kk++) {
                float zv = sZ[(k + kk) * 36 + col];
                #pragma unroll
                for (int r = 0; r < 8; r++)
                    acc[r] += (&a4[r].x)[kk] * zv;
            }
        }
        __syncthreads();
    }

    #pragma unroll
    for (int r = 0; r < 8; r++)
        L[(size_t)(rb + rowg * 8 + r) * 32 + col] = acc[r];
}

// -------------------- fused z = rbf(X, q).T @ Lambda (v2: two-phase) --------
// Block: 128 queries x 32 cols; x streamed in chunks of 64.
// Phase 1: d2/P tile (64x x 128q) with 8q x 4x register tiles (x strided 16).
// Phase 2: z += P @ Lambda with 4q x 4c register tiles.
#define PSD 132   // P tile row stride (floats): 128 + 4

template <int D>
__device__ __forceinline__ void fused_task(
    char* smem_raw,
    const float* __restrict__ Xg, const float* __restrict__ Qg,
    const float* __restrict__ Lg, const float* __restrict__ Xn,
    const float* __restrict__ Qn, float* __restrict__ Zg, int qb) {

    constexpr int SD = D + 4;            // SD/4 odd (17 / 25) -> conflict-free strided rows
    float* sQ  = (float*)smem_raw;       // 128 * SD
    float* sX  = sQ + 128 * SD;          // 64 * SD
    float* sP  = sX + 64 * SD;           // 64 * PSD
    float* sL  = sP + 64 * PSD;          // 64 * 32
    float* sQn = sL + 64 * 32;           // 128
    float* sXn = sQn + 128;              // 64

    const int tid = threadIdx.x;
    const int xg  = tid & 15;            // phase1: x rows {xg + 16m}
    const int qg  = tid >> 4;            // phase1: q rows qg*8 .. qg*8+7
    const int cg  = tid & 7;             // phase2: cols cg*4 .. +3
    const int qg2 = tid >> 3;            // phase2: q rows qg2*4 .. +3

    // load Q tile + Q norms (once per block)
    #pragma unroll
    for (int f = tid; f < 128 * (D / 4); f += 256) {
        int r = f / (D / 4), c = (f % (D / 4)) * 4;
        *(float4*)&sQ[r * SD + c] = *(const float4*)&Qg[(size_t)(qb + r) * D + c];
    }
    if (tid < 128) sQn[tid] = Qn[qb + tid];

    float zacc[4][4];
    #pragma unroll
    for (int i = 0; i < 4; i++)
        #pragma unroll
        for (int j = 0; j < 4; j++) zacc[i][j] = 0.f;

    for (int xb = 0; xb < N; xb += 64) {
        __syncthreads();   // prev phase2 done before overwriting sX/sL/sP

        // load chunk: X rows, Lambda rows, X norms
        #pragma unroll
        for (int f = tid; f < 64 * (D / 4); f += 256) {
            int r = f / (D / 4), c = (f % (D / 4)) * 4;
            *(float4*)&sX[r * SD + c] = *(const float4*)&Xg[(size_t)(xb + r) * D + c];
        }
        #pragma unroll
        for (int f = tid; f < 64 * 8; f += 256) {
            int r = f >> 3, c = (f & 7) * 4;
            *(float4*)&sL[r * 32 + c] = *(const float4*)&Lg[(size_t)(xb + r) * 32 + c];
        }
        if (tid < 64) sXn[tid] = Xn[xb + tid];
        __syncthreads();

        // ---- phase 1: dot products (8q x 4x per thread) ----
        float dot[8][4];
        #pragma unroll
        for (int r = 0; r < 8; r++)
            #pragma unroll
            for (int m = 0; m < 4; m++) dot[r][m] = 0.f;

        #pragma unroll 2
        for (int k4 = 0; k4 < D / 4; k4++) {
            float4 xv[4], qv[8];
            #pragma unroll
            for (int m = 0; m < 4; m++)
                xv[m] = *(const float4*)&sX[(xg + 16 * m) * SD + 4 * k4];
            #pragma unroll
            for (int r = 0; r < 8; r++)
                qv[r] = *(const float4*)&sQ[(qg * 8 + r) * SD + 4 * k4];
            #pragma unroll
            for (int r = 0; r < 8; r++)
                #pragma unroll
                for (int m = 0; m < 4; m++) {
                    dot[r][m] = fmaf(qv[r].x, xv[m].x, dot[r][m]);
                    dot[r][m] = fmaf(qv[r].y, xv[m].y, dot[r][m]);
                    dot[r][m] = fmaf(qv[r].z, xv[m].z, dot[r][m]);
                    dot[r][m] = fmaf(qv[r].w, xv[m].w, dot[r][m]);
                }
        }

        // exp -> P tile (layout P[x][q])
        #pragma unroll
        for (int m = 0; m < 4; m++) {
            float xn = sXn[xg + 16 * m];
            float pr[8];
            #pragma unroll
            for (int r = 0; r < 8; r++) {
                float d2 = sQn[qg * 8 + r] + xn - 2.f * dot[r][m];
                d2 = fmaxf(d2, 0.f);
                pr[r] = __expf(-0.0078125f * d2);   // 1/(2*8*8)
            }
            *(float4*)&sP[(xg + 16 * m) * PSD + qg * 8] =
                make_float4(pr[0], pr[1], pr[2], pr[3]);
            *(float4*)&sP[(xg + 16 * m) * PSD + qg * 8 + 4] =
                make_float4(pr[4], pr[5], pr[6], pr[7]);
        }
        __syncthreads();

        // ---- phase 2: z += P @ Lambda (4q x 4c per thread) ----
        #pragma unroll 4
        for (int x = 0; x < 64; x++) {
            float4 pv = *(const float4*)&sP[x * PSD + qg2 * 4];
            float4 lv = *(const float4*)&sL[x * 32 + cg * 4];
            #pragma unroll
            for (int j = 0; j < 4; j++) {
                float l = (&lv.x)[j];
                zacc[0][j] = fmaf(pv.x, l, zacc[0][j]);
                zacc[1][j] = fmaf(pv.y, l, zacc[1][j]);
                zacc[2][j] = fmaf(pv.z, l, zacc[2][j]);
                zacc[3][j] = fmaf(pv.w, l, zacc[3][j]);
            }
        }
    }

    // write z
    #pragma unroll
    for (int i = 0; i < 4; i++) {
        float4 v = make_float4(zacc[i][0], zacc[i][1], zacc[i][2], zacc[i][3]);
        *(float4*)&Zg[(size_t)(qb + qg2 * 4 + i) * 32 + cg * 4] = v;
    }
}

// dyn smem: max over tasks = task1 (D=96): (128+64)*100*4 + 64*132*4 + 64*32*4 + 192*4
#define FUSED_SMEM ((192 * 100 + 64 * PSD + 64 * 32 + 192) * 4)

__global__ __launch_bounds__(256, 1) void fused2_kernel(
    const float* __restrict__ Xm, const float* __restrict__ Xv) {
    extern __shared__ char smem[];
    int task = blockIdx.x >> 6;
    int qb   = (blockIdx.x & 63) * 128;
    if (task == 0)
        fused_task<64>(smem, Xm, g_xqm, g_Lm, g_Xnm, g_qnm, g_zm, qb);
    else
        fused_task<96>(smem, Xv, g_xqv, g_Lv, g_Xnv, g_qnv, g_zv, qb);
}

// -------------------- combine ----------------------------------------------
__global__ void combine_kernel(const float* __restrict__ y_mean,
                               const float* __restrict__ y_var,
                               float* __restrict__ out) {
    int i = blockIdx.x * blockDim.x + threadIdx.x;
    if (i < N * 32)
        out[i] = (y_mean[i] + g_zm[i]) + (y_var[i] + g_zv[i]);
}

// -------------------- launch ------------------------------------------------
extern "C" void kernel_launch(void* const* d_in, const int* in_sizes, int n_in,
                              void* d_out, int out_size) {
    const float* x_mu   = (const float*)d_in[0];
    const float* y_eta  = (const float*)d_in[1];
    const float* y_mean = (const float*)d_in[2];
    const float* y_var  = (const float*)d_in[3];
    const float* X_mean = (const float*)d_in[4];
    const float* X_var  = (const float*)d_in[5];
    const float* Z_mean = (const float*)d_in[6];
    const float* Z_var  = (const float*)d_in[7];
    const float* kMi    = (const float*)d_in[8];
    const float* kVi    = (const float*)d_in[9];
    float* out = (float*)d_out;

    cudaFuncSetAttribute(fused2_kernel,
                         cudaFuncAttributeMaxDynamicSharedMemorySize, FUSED_SMEM);

    prep_q_kernel<<<(N * 32 + 255) / 256, 256>>>(x_mu, y_eta, y_mean, y_var);
    prep_X_kernel<<<(N * 32 + 255) / 256, 256>>>(X_mean, X_var);

    lambda_gemm_kernel<<<dim3(N / 64, 2), 256>>>(kMi, Z_mean, kVi, Z_var);

    fused2_kernel<<<128, 256, FUSED_SMEM>>>(X_mean, X_var);

    combine_kernel<<<(N * 32 + 255) / 256, 256>>>(y_mean, y_var, out);
}

// round 4
// speedup vs baseline: 2.4641x; 1.0177x over previous
#include <cuda_runtime.h>

// ---------------------------------------------------------------------------
// CondTransportKernel: fused GP conditional-transport map.
//   out [8192,32] f32 = y_mean + y_var + z_mean + z_var
//   z_* = rbf(X_*, q_*).T @ (kXX*_inv @ Z_*)
// ---------------------------------------------------------------------------

#define N 8192

// -------------------- device scratch (static, no allocations) --------------
__device__ float g_xqm[N * 64];   // query features, mean map  [x_mu | y_mean+y_var]
__device__ float g_xqv[N * 96];   // query features, var  map  [x_mu | .01*flip(y_eta) | y_mean+y_var]
__device__ float g_qnm[N];        // |q|^2 mean map
__device__ float g_qnv[N];        // |q|^2 var map
__device__ float g_Xnm[N];        // |X_mean row|^2
__device__ float g_Xnv[N];        // |X_var  row|^2
__device__ float g_Lm[N * 32];    // Lambda_mean
__device__ float g_Lv[N * 32];    // Lambda_var
__device__ float g_zm[N * 32];    // z_mean
__device__ float g_zv[N * 32];    // z_var

// -------------------- prep: build query features + norms -------------------
__global__ void prep_q_kernel(const float* __restrict__ x_mu,
                              const float* __restrict__ y_eta,
                              const float* __restrict__ y_mean,
                              const float* __restrict__ y_var) {
    int warp = (blockIdx.x * blockDim.x + threadIdx.x) >> 5;
    int lane = threadIdx.x & 31;
    if (warp >= N) return;
    int q = warp;
    float a = x_mu[q * 32 + lane];
    float m = y_mean[q * 32 + lane] + y_var[q * 32 + lane];
    float e = 0.01f * y_eta[(N - 1 - q) * 32 + lane];

    g_xqm[q * 64 + lane]      = a;
    g_xqm[q * 64 + 32 + lane] = m;
    g_xqv[q * 96 + lane]      = a;
    g_xqv[q * 96 + 32 + lane] = e;
    g_xqv[q * 96 + 64 + lane] = m;

    float nm = a * a + m * m;
    float nv = nm + e * e;
    #pragma unroll
    for (int off = 16; off; off >>= 1) {
        nm += __shfl_xor_sync(0xffffffffu, nm, off);
        nv += __shfl_xor_sync(0xffffffffu, nv, off);
    }
    if (lane == 0) { g_qnm[q] = nm; g_qnv[q] = nv; }
}

__global__ void prep_X_kernel(const float* __restrict__ Xm,
                              const float* __restrict__ Xv) {
    int warp = (blockIdx.x * blockDim.x + threadIdx.x) >> 5;
    int lane = threadIdx.x & 31;
    if (warp >= N) return;
    int i = warp;
    float nm = 0.f;
    #pragma unroll
    for (int c = 0; c < 64; c += 32) {
        float v = Xm[(size_t)i * 64 + c + lane];
        nm += v * v;
    }
    float nv = 0.f;
    #pragma unroll
    for (int c = 0; c < 96; c += 32) {
        float v = Xv[(size_t)i * 96 + c + lane];
        nv += v * v;
    }
    #pragma unroll
    for (int off = 16; off; off >>= 1) {
        nm += __shfl_xor_sync(0xffffffffu, nm, off);
        nv += __shfl_xor_sync(0xffffffffu, nv, off);
    }
    if (lane == 0) { g_Xnm[i] = nm; g_Xnv[i] = nv; }
}

// -------------------- Lambda = kXX_inv @ Z  (M=8192, N=32, K=8192) ----------
__global__ __launch_bounds__(256) void lambda_gemm_kernel(
    const float* __restrict__ A0, const float* __restrict__ Z0,
    const float* __restrict__ A1, const float* __restrict__ Z1) {
    const float* A = blockIdx.y ? A1 : A0;
    const float* Z = blockIdx.y ? Z1 : Z0;
    float* L       = blockIdx.y ? g_Lv : g_Lm;

    __shared__ __align__(16) float sA[64 * 68];
    __shared__ __align__(16) float sZ[64 * 36];

    const int tid  = threadIdx.x;
    const int col  = tid & 31;
    const int rowg = tid >> 5;
    const int rb   = blockIdx.x * 64;

    float acc[8];
    #pragma unroll
    for (int r = 0; r < 8; r++) acc[r] = 0.f;

    for (int k0 = 0; k0 < N; k0 += 64) {
        {
            int idx = tid;
            #pragma unroll
            for (int it = 0; it < 4; it++, idx += 256) {
                int r = idx >> 4, v = idx & 15;
                float4 av = *(const float4*)&A[(size_t)(rb + r) * N + k0 + v * 4];
                *(float4*)&sA[r * 68 + v * 4] = av;
            }
        }
        {
            int idx = tid;
            #pragma unroll
            for (int it = 0; it < 2; it++, idx += 256) {
                int r = idx >> 3, v = idx & 7;
                float4 zv = *(const float4*)&Z[(size_t)(k0 + r) * 32 + v * 4];
                *(float4*)&sZ[r * 36 + v * 4] = zv;
            }
        }
        __syncthreads();

        #pragma unroll
        for (int k = 0; k < 64; k += 4) {
            float4 a4[8];
            #pragma unroll
            for (int r = 0; r < 8; r++)
                a4[r] = *(const float4*)&sA[(rowg * 8 + r) * 68 + k];
            #pragma unroll
            for (int kk = 0; kk < 4; kk++) {
                float zv = sZ[(k + kk) * 36 + col];
                #pragma unroll
                for (int r = 0; r < 8; r++)
                    acc[r] += (&a4[r].x)[kk] * zv;
            }
        }
        __syncthreads();
    }

    #pragma unroll
    for (int r = 0; r < 8; r++)
        L[(size_t)(rb + rowg * 8 + r) * 32 + col] = acc[r];
}

// -------------------- fused z = rbf(X, q).T @ Lambda (v2: two-phase) --------
// Block: 128 queries x 32 cols; x streamed in chunks of 64.
// Phase 1: d2/P tile (64x x 128q) with 8q x 4x register tiles (x strided 16).
// Phase 2: z += P @ Lambda with 4q x 4c register tiles.
#define PSD 132   // P tile row stride (floats): 128 + 4

template <int D>
__device__ __forceinline__ void fused_task(
    char* smem_raw,
    const float* __restrict__ Xg, const float* __restrict__ Qg,
    const float* __restrict__ Lg, const float* __restrict__ Xn,
    const float* __restrict__ Qn, float* __restrict__ Zg, int qb) {

    constexpr int SD = D + 4;            // SD/4 odd (17 / 25) -> conflict-free strided rows
    float* sQ  = (float*)smem_raw;       // 128 * SD
    float* sX  = sQ + 128 * SD;          // 64 * SD
    float* sP  = sX + 64 * SD;           // 64 * PSD
    float* sL  = sP + 64 * PSD;          // 64 * 32
    float* sQn = sL + 64 * 32;           // 128
    float* sXn = sQn + 128;              // 64

    const int tid = threadIdx.x;
    const int xg  = tid & 15;            // phase1: x rows {xg + 16m}
    const int qg  = tid >> 4;            // phase1: q rows qg*8 .. qg*8+7
    const int cg  = tid & 7;             // phase2: cols cg*4 .. +3
    const int qg2 = tid >> 3;            // phase2: q rows qg2*4 .. +3

    // load Q tile + Q norms (once per block)
    #pragma unroll
    for (int f = tid; f < 128 * (D / 4); f += 256) {
        int r = f / (D / 4), c = (f % (D / 4)) * 4;
        *(float4*)&sQ[r * SD + c] = *(const float4*)&Qg[(size_t)(qb + r) * D + c];
    }
    if (tid < 128) sQn[tid] = Qn[qb + tid];

    float zacc[4][4];
    #pragma unroll
    for (int i = 0; i < 4; i++)
        #pragma unroll
        for (int j = 0; j < 4; j++) zacc[i][j] = 0.f;

    for (int xb = 0; xb < N; xb += 64) {
        __syncthreads();   // prev phase2 done before overwriting sX/sL/sP

        // load chunk: X rows, Lambda rows, X norms
        #pragma unroll
        for (int f = tid; f < 64 * (D / 4); f += 256) {
            int r = f / (D / 4), c = (f % (D / 4)) * 4;
            *(float4*)&sX[r * SD + c] = *(const float4*)&Xg[(size_t)(xb + r) * D + c];
        }
        #pragma unroll
        for (int f = tid; f < 64 * 8; f += 256) {
            int r = f >> 3, c = (f & 7) * 4;
            *(float4*)&sL[r * 32 + c] = *(const float4*)&Lg[(size_t)(xb + r) * 32 + c];
        }
        if (tid < 64) sXn[tid] = Xn[xb + tid];
        __syncthreads();

        // ---- phase 1: dot products (8q x 4x per thread) ----
        float dot[8][4];
        #pragma unroll
        for (int r = 0; r < 8; r++)
            #pragma unroll
            for (int m = 0; m < 4; m++) dot[r][m] = 0.f;

        #pragma unroll 2
        for (int k4 = 0; k4 < D / 4; k4++) {
            float4 xv[4], qv[8];
            #pragma unroll
            for (int m = 0; m < 4; m++)
                xv[m] = *(const float4*)&sX[(xg + 16 * m) * SD + 4 * k4];
            #pragma unroll
            for (int r = 0; r < 8; r++)
                qv[r] = *(const float4*)&sQ[(qg * 8 + r) * SD + 4 * k4];
            #pragma unroll
            for (int r = 0; r < 8; r++)
                #pragma unroll
                for (int m = 0; m < 4; m++) {
                    dot[r][m] = fmaf(qv[r].x, xv[m].x, dot[r][m]);
                    dot[r][m] = fmaf(qv[r].y, xv[m].y, dot[r][m]);
                    dot[r][m] = fmaf(qv[r].z, xv[m].z, dot[r][m]);
                    dot[r][m] = fmaf(qv[r].w, xv[m].w, dot[r][m]);
                }
        }

        // exp -> P tile (layout P[x][q])
        #pragma unroll
        for (int m = 0; m < 4; m++) {
            float xn = sXn[xg + 16 * m];
            float pr[8];
            #pragma unroll
            for (int r = 0; r < 8; r++) {
                float d2 = sQn[qg * 8 + r] + xn - 2.f * dot[r][m];
                d2 = fmaxf(d2, 0.f);
                pr[r] = __expf(-0.0078125f * d2);   // 1/(2*8*8)
            }
            *(float4*)&sP[(xg + 16 * m) * PSD + qg * 8] =
                make_float4(pr[0], pr[1], pr[2], pr[3]);
            *(float4*)&sP[(xg + 16 * m) * PSD + qg * 8 + 4] =
                make_float4(pr[4], pr[5], pr[6], pr[7]);
        }
        __syncthreads();

        // ---- phase 2: z += P @ Lambda (4q x 4c per thread) ----
        #pragma unroll 4
        for (int x = 0; x < 64; x++) {
            float4 pv = *(const float4*)&sP[x * PSD + qg2 * 4];
            float4 lv = *(const float4*)&sL[x * 32 + cg * 4];
            #pragma unroll
            for (int j = 0; j < 4; j++) {
                float l = (&lv.x)[j];
                zacc[0][j] = fmaf(pv.x, l, zacc[0][j]);
                zacc[1][j] = fmaf(pv.y, l, zacc[1][j]);
                zacc[2][j] = fmaf(pv.z, l, zacc[2][j]);
                zacc[3][j] = fmaf(pv.w, l, zacc[3][j]);
            }
        }
    }

    // write z
    #pragma unroll
    for (int i = 0; i < 4; i++) {
        float4 v = make_float4(zacc[i][0], zacc[i][1], zacc[i][2], zacc[i][3]);
        *(float4*)&Zg[(size_t)(qb + qg2 * 4 + i) * 32 + cg * 4] = v;
    }
}

// dyn smem: max over tasks = task1 (D=96): (128+64)*100*4 + 64*132*4 + 64*32*4 + 192*4
#define FUSED_SMEM ((192 * 100 + 64 * PSD + 64 * 32 + 192) * 4)

__global__ __launch_bounds__(256, 1) void fused2_kernel(
    const float* __restrict__ Xm, const float* __restrict__ Xv) {
    extern __shared__ char smem[];
    int task = blockIdx.x >> 6;
    int qb   = (blockIdx.x & 63) * 128;
    if (task == 0)
        fused_task<64>(smem, Xm, g_xqm, g_Lm, g_Xnm, g_qnm, g_zm, qb);
    else
        fused_task<96>(smem, Xv, g_xqv, g_Lv, g_Xnv, g_qnv, g_zv, qb);
}

// -------------------- combine ----------------------------------------------
__global__ void combine_kernel(const float* __restrict__ y_mean,
                               const float* __restrict__ y_var,
                               float* __restrict__ out) {
    int i = blockIdx.x * blockDim.x + threadIdx.x;
    if (i < N * 32)
        out[i] = (y_mean[i] + g_zm[i]) + (y_var[i] + g_zv[i]);
}

// -------------------- launch ------------------------------------------------
extern "C" void kernel_launch(void* const* d_in, const int* in_sizes, int n_in,
                              void* d_out, int out_size) {
    const float* x_mu   = (const float*)d_in[0];
    const float* y_eta  = (const float*)d_in[1];
    const float* y_mean = (const float*)d_in[2];
    const float* y_var  = (const float*)d_in[3];
    const float* X_mean = (const float*)d_in[4];
    const float* X_var  = (const float*)d_in[5];
    const float* Z_mean = (const float*)d_in[6];
    const float* Z_var  = (const float*)d_in[7];
    const float* kMi    = (const float*)d_in[8];
    const float* kVi    = (const float*)d_in[9];
    float* out = (float*)d_out;

    cudaFuncSetAttribute(fused2_kernel,
                         cudaFuncAttributeMaxDynamicSharedMemorySize, FUSED_SMEM);

    prep_q_kernel<<<(N * 32 + 255) / 256, 256>>>(x_mu, y_eta, y_mean, y_var);
    prep_X_kernel<<<(N * 32 + 255) / 256, 256>>>(X_mean, X_var);

    lambda_gemm_kernel<<<dim3(N / 64, 2), 256>>>(kMi, Z_mean, kVi, Z_var);

    fused2_kernel<<<128, 256, FUSED_SMEM>>>(X_mean, X_var);

    combine_kernel<<<(N * 32 + 255) / 256, 256>>>(y_mean, y_var, out);
}

// round 6
// speedup vs baseline: 3.9218x; 1.5916x over previous
#include <cuda_runtime.h>
#include <cuda_bf16.h>
#include <cstdint>

#define N 8192

// -------------------- device scratch ---------------------------------------
__device__ float g_xqm[N * 64];
__device__ float g_xqv[N * 96];
__device__ float g_qnm[N], g_qnv[N], g_Xnm[N], g_Xnv[N];
__device__ float g_Lm[N * 32], g_Lv[N * 32];
__device__ float g_zm[N * 32], g_zv[N * 32];
__device__ __nv_bfloat16 g_Xmh[N * 64], g_Xml[N * 64];
__device__ __nv_bfloat16 g_Xvh[N * 96], g_Xvl[N * 96];
__device__ __nv_bfloat16 g_Lth0[32 * N], g_Ltl0[32 * N];
__device__ __nv_bfloat16 g_Lth1[32 * N], g_Ltl1[32 * N];

// -------------------- mma helpers (sm_80+ HMMA, no 'a' features) ------------
__device__ __forceinline__ void mma_bf16(float c[4], const uint32_t a[4],
                                         uint32_t b0, uint32_t b1) {
    asm volatile(
        "mma.sync.aligned.m16n8k16.row.col.f32.bf16.bf16.f32 "
        "{%0,%1,%2,%3}, {%4,%5,%6,%7}, {%8,%9}, {%0,%1,%2,%3};"
        : "+f"(c[0]), "+f"(c[1]), "+f"(c[2]), "+f"(c[3])
        : "r"(a[0]), "r"(a[1]), "r"(a[2]), "r"(a[3]), "r"(b0), "r"(b1));
}
__device__ __forceinline__ uint32_t packbf(float lo, float hi) {
    uint32_t r;
    asm("cvt.rn.bf16x2.f32 %0, %1, %2;" : "=r"(r) : "f"(hi), "f"(lo));
    return r;
}
__device__ __forceinline__ uint32_t ldsw(const __nv_bfloat16* p) {
    return *(const uint32_t*)p;
}

// -------------------- prep kernels ------------------------------------------
__global__ void prep_q_kernel(const float* __restrict__ x_mu,
                              const float* __restrict__ y_eta,
                              const float* __restrict__ y_mean,
                              const float* __restrict__ y_var) {
    int q = (blockIdx.x * blockDim.x + threadIdx.x) >> 5;
    int lane = threadIdx.x & 31;
    if (q >= N) return;
    float a = x_mu[q * 32 + lane];
    float m = y_mean[q * 32 + lane] + y_var[q * 32 + lane];
    float e = 0.01f * y_eta[(N - 1 - q) * 32 + lane];
    g_xqm[q * 64 + lane] = a;       g_xqm[q * 64 + 32 + lane] = m;
    g_xqv[q * 96 + lane] = a;       g_xqv[q * 96 + 32 + lane] = e;
    g_xqv[q * 96 + 64 + lane] = m;
    float nm = a * a + m * m, nv = nm + e * e;
    #pragma unroll
    for (int o = 16; o; o >>= 1) {
        nm += __shfl_xor_sync(0xffffffffu, nm, o);
        nv += __shfl_xor_sync(0xffffffffu, nv, o);
    }
    if (lane == 0) { g_qnm[q] = nm; g_qnv[q] = nv; }
}

__global__ void prep_X_kernel(const float* __restrict__ Xm,
                              const float* __restrict__ Xv) {
    int i = (blockIdx.x * blockDim.x + threadIdx.x) >> 5;
    int lane = threadIdx.x & 31;
    if (i >= N) return;
    float nm = 0.f, nv = 0.f;
    #pragma unroll
    for (int c = 0; c < 64; c += 32) {
        float v = Xm[(size_t)i * 64 + c + lane];
        nm += v * v;
        __nv_bfloat16 h = __float2bfloat16(v);
        g_Xmh[(size_t)i * 64 + c + lane] = h;
        g_Xml[(size_t)i * 64 + c + lane] = __float2bfloat16(v - __bfloat162float(h));
    }
    #pragma unroll
    for (int c = 0; c < 96; c += 32) {
        float v = Xv[(size_t)i * 96 + c + lane];
        nv += v * v;
        __nv_bfloat16 h = __float2bfloat16(v);
        g_Xvh[(size_t)i * 96 + c + lane] = h;
        g_Xvl[(size_t)i * 96 + c + lane] = __float2bfloat16(v - __bfloat162float(h));
    }
    #pragma unroll
    for (int o = 16; o; o >>= 1) {
        nm += __shfl_xor_sync(0xffffffffu, nm, o);
        nv += __shfl_xor_sync(0xffffffffu, nv, o);
    }
    if (lane == 0) { g_Xnm[i] = nm; g_Xnv[i] = nv; }
}

// -------------------- Lambda = kXX_inv @ Z (SIMT, known-good) ---------------
__global__ __launch_bounds__(256) void lambda_gemm_kernel(
    const float* __restrict__ A0, const float* __restrict__ Z0,
    const float* __restrict__ A1, const float* __restrict__ Z1) {
    const float* A = blockIdx.y ? A1 : A0;
    const float* Z = blockIdx.y ? Z1 : Z0;
    float* L       = blockIdx.y ? g_Lv : g_Lm;
    __shared__ __align__(16) float sA[64 * 68];
    __shared__ __align__(16) float sZ[64 * 36];
    const int tid = threadIdx.x, col = tid & 31, rowg = tid >> 5;
    const int rb = blockIdx.x * 64;
    float acc[8];
    #pragma unroll
    for (int r = 0; r < 8; r++) acc[r] = 0.f;
    for (int k0 = 0; k0 < N; k0 += 64) {
        int idx = tid;
        #pragma unroll
        for (int it = 0; it < 4; it++, idx += 256) {
            int r = idx >> 4, v = idx & 15;
            *(float4*)&sA[r * 68 + v * 4] =
                *(const float4*)&A[(size_t)(rb + r) * N + k0 + v * 4];
        }
        idx = tid;
        #pragma unroll
        for (int it = 0; it < 2; it++, idx += 256) {
            int r = idx >> 3, v = idx & 7;
            *(float4*)&sZ[r * 36 + v * 4] =
                *(const float4*)&Z[(size_t)(k0 + r) * 32 + v * 4];
        }
        __syncthreads();
        #pragma unroll
        for (int k = 0; k < 64; k += 4) {
            float4 a4[8];
            #pragma unroll
            for (int r = 0; r < 8; r++)
                a4[r] = *(const float4*)&sA[(rowg * 8 + r) * 68 + k];
            #pragma unroll
            for (int kk = 0; kk < 4; kk++) {
                float zv = sZ[(k + kk) * 36 + col];
                #pragma unroll
                for (int r = 0; r < 8; r++)
                    acc[r] += (&a4[r].x)[kk] * zv;
            }
        }
        __syncthreads();
    }
    #pragma unroll
    for (int r = 0; r < 8; r++)
        L[(size_t)(rb + rowg * 8 + r) * 32 + col] = acc[r];
}

// Lambda -> transposed bf16 hi/lo [32][N]
__global__ void lsplit_kernel() {
    int idx = blockIdx.x * blockDim.x + threadIdx.x;
    int t = idx >= 32 * N;
    int j = idx - t * 32 * N;
    if (j >= 32 * N) return;
    int n = j / N, k = j - n * N;
    float v = (t ? g_Lv : g_Lm)[(size_t)k * 32 + n];
    __nv_bfloat16 h = __float2bfloat16(v);
    (t ? g_Lth1 : g_Lth0)[(size_t)n * N + k] = h;
    (t ? g_Ltl1 : g_Ltl0)[(size_t)n * N + k] =
        __float2bfloat16(v - __bfloat162float(h));
}

// -------------------- fused HMMA kernel -------------------------------------
// Per CTA: 128 queries, stream x in 64-chunks.
// Warp w owns q rows [16w,16w+16). Phase1: D1 = Q.X^T (8 n-tiles of 8 x).
// Epilogue: exp on C-frags, repack into A-frags (no SMEM round-trip for P).
// Phase2: z[16x32] += P.Lambda^T with B frags from sLt (k-contiguous).
template <int D>
__device__ void ftc(char* smraw, const __nv_bfloat16* Xh, const __nv_bfloat16* Xl,
                    const float* Qg, const __nv_bfloat16* Lth,
                    const __nv_bfloat16* Ltl, const float* Xn,
                    const float* Qn, float* Zg, int qb) {
    constexpr int QS = D + 8;                 // bf16 stride: (QS/2) words, odd -> cf
    __nv_bfloat16* sQh = (__nv_bfloat16*)smraw;
    __nv_bfloat16* sQl = sQh + 128 * QS;
    __nv_bfloat16* sXh = sQl + 128 * QS;
    __nv_bfloat16* sXl = sXh + 64 * QS;
    __nv_bfloat16* sLh = sXl + 64 * QS;       // [32][72]
    __nv_bfloat16* sLl = sLh + 32 * 72;
    float* sXn = (float*)(sLl + 32 * 72);

    const int tid = threadIdx.x;
    const int lane = tid & 31, w = tid >> 5;
    const int t = lane & 3, qr = lane >> 2;
    const int wq0 = w * 16;

    // split Q -> SMEM bf16 hi/lo
    for (int i = tid; i < 128 * D; i += 256) {
        int r = i / D, c = i - r * D;
        float v = Qg[(size_t)(qb + r) * D + c];
        __nv_bfloat16 h = __float2bfloat16(v);
        sQh[r * QS + c] = h;
        sQl[r * QS + c] = __float2bfloat16(v - __bfloat162float(h));
    }
    const float qn0 = Qn[qb + wq0 + qr];
    const float qn1 = Qn[qb + wq0 + qr + 8];

    float zc[4][4];
    #pragma unroll
    for (int i = 0; i < 4; i++)
        #pragma unroll
        for (int j = 0; j < 4; j++) zc[i][j] = 0.f;

    for (int cb = 0; cb < 128; cb++) {
        const int xb = cb * 64;
        // ---- stage chunk: X hi/lo (uint2 words), Lt hi/lo, x norms ----
        #pragma unroll
        for (int i = tid; i < 64 * (D / 4); i += 256) {
            int r = i / (D / 4), p = i - r * (D / 4);
            uint2 vh = ((const uint2*)Xh)[(size_t)(xb + r) * (D / 4) + p];
            uint2 vl = ((const uint2*)Xl)[(size_t)(xb + r) * (D / 4) + p];
            *(uint2*)(sXh + r * QS + p * 4) = vh;
            *(uint2*)(sXl + r * QS + p * 4) = vl;
        }
        #pragma unroll
        for (int i = tid; i < 32 * 16; i += 256) {
            int n = i >> 4, p = i & 15;
            uint2 vh = ((const uint2*)Lth)[(size_t)n * (N / 4) + xb / 4 + p];
            uint2 vl = ((const uint2*)Ltl)[(size_t)n * (N / 4) + xb / 4 + p];
            *(uint2*)(sLh + n * 72 + p * 4) = vh;
            *(uint2*)(sLl + n * 72 + p * 4) = vl;
        }
        if (tid < 64) sXn[tid] = Xn[xb + tid];
        __syncthreads();

        // ---- phase 1: D1[16q x 64x] ----
        float c1[8][4];
        #pragma unroll
        for (int i = 0; i < 8; i++)
            #pragma unroll
            for (int j = 0; j < 4; j++) c1[i][j] = 0.f;

        #pragma unroll
        for (int kt = 0; kt < D / 16; kt++) {
            const int k0 = kt * 16 + 2 * t;
            uint32_t ah[4], al[4];
            ah[0] = ldsw(sQh + (wq0 + qr) * QS + k0);
            ah[1] = ldsw(sQh + (wq0 + qr + 8) * QS + k0);
            ah[2] = ldsw(sQh + (wq0 + qr) * QS + k0 + 8);
            ah[3] = ldsw(sQh + (wq0 + qr + 8) * QS + k0 + 8);
            al[0] = ldsw(sQl + (wq0 + qr) * QS + k0);
            al[1] = ldsw(sQl + (wq0 + qr + 8) * QS + k0);
            al[2] = ldsw(sQl + (wq0 + qr) * QS + k0 + 8);
            al[3] = ldsw(sQl + (wq0 + qr + 8) * QS + k0 + 8);
            #pragma unroll
            for (int nt = 0; nt < 8; nt++) {
                const int xr = nt * 8 + qr;
                uint32_t bh0 = ldsw(sXh + xr * QS + k0);
                uint32_t bh1 = ldsw(sXh + xr * QS + k0 + 8);
                uint32_t bl0 = ldsw(sXl + xr * QS + k0);
                uint32_t bl1 = ldsw(sXl + xr * QS + k0 + 8);
                mma_bf16(c1[nt], ah, bh0, bh1);
                mma_bf16(c1[nt], ah, bl0, bl1);
                mma_bf16(c1[nt], al, bh0, bh1);
            }
        }

        // ---- epilogue: exp -> P fragments (C m16n8 -> A m16k16 repack) ----
        uint32_t Ph[4][4], Pl[4][4];
        #pragma unroll
        for (int kt2 = 0; kt2 < 4; kt2++) {
            #pragma unroll
            for (int s = 0; s < 2; s++) {
                const int nt = 2 * kt2 + s;
                const int x0 = nt * 8 + 2 * t;
                float xna = sXn[x0], xnb = sXn[x0 + 1];
                float p0 = __expf(-0.0078125f * fmaxf(qn0 + xna - 2.f * c1[nt][0], 0.f));
                float p1 = __expf(-0.0078125f * fmaxf(qn0 + xnb - 2.f * c1[nt][1], 0.f));
                float p2 = __expf(-0.0078125f * fmaxf(qn1 + xna - 2.f * c1[nt][2], 0.f));
                float p3 = __expf(-0.0078125f * fmaxf(qn1 + xnb - 2.f * c1[nt][3], 0.f));
                uint32_t w0 = packbf(p0, p1);
                uint32_t w1 = packbf(p2, p3);
                float r0 = p0 - __uint_as_float(w0 << 16);
                float r1 = p1 - __uint_as_float(w0 & 0xffff0000u);
                float r2 = p2 - __uint_as_float(w1 << 16);
                float r3 = p3 - __uint_as_float(w1 & 0xffff0000u);
                Ph[kt2][2 * s]     = w0;
                Ph[kt2][2 * s + 1] = w1;
                Pl[kt2][2 * s]     = packbf(r0, r1);
                Pl[kt2][2 * s + 1] = packbf(r2, r3);
            }
        }

        // ---- phase 2: z += P . Lambda^T ----
        #pragma unroll
        for (int kt2 = 0; kt2 < 4; kt2++) {
            const int k0 = kt2 * 16 + 2 * t;
            #pragma unroll
            for (int nt = 0; nt < 4; nt++) {
                const int nc = nt * 8 + qr;
                uint32_t bh0 = ldsw(sLh + nc * 72 + k0);
                uint32_t bh1 = ldsw(sLh + nc * 72 + k0 + 8);
                uint32_t bl0 = ldsw(sLl + nc * 72 + k0);
                uint32_t bl1 = ldsw(sLl + nc * 72 + k0 + 8);
                mma_bf16(zc[nt], Ph[kt2], bh0, bh1);
                mma_bf16(zc[nt], Ph[kt2], bl0, bl1);
                mma_bf16(zc[nt], Pl[kt2], bh0, bh1);
            }
        }
        __syncthreads();
    }

    // ---- write z ----
    const int row0 = qb + wq0 + qr;
    #pragma unroll
    for (int nt = 0; nt < 4; nt++) {
        const int col = nt * 8 + 2 * t;
        Zg[(size_t)row0 * 32 + col]           = zc[nt][0];
        Zg[(size_t)row0 * 32 + col + 1]       = zc[nt][1];
        Zg[(size_t)(row0 + 8) * 32 + col]     = zc[nt][2];
        Zg[(size_t)(row0 + 8) * 32 + col + 1] = zc[nt][3];
    }
}

// smem bytes for D=96: (2*128*104 + 2*64*104 + 2*32*72)*2 + 64*4 = 89344
#define FUSED_SMEM 89600

__global__ __launch_bounds__(256, 1) void fusedtc_kernel() {
    extern __shared__ char sm[];
    int task = blockIdx.x >> 6;
    int qb   = (blockIdx.x & 63) * 128;
    if (task == 0)
        ftc<64>(sm, g_Xmh, g_Xml, g_xqm, g_Lth0, g_Ltl0, g_Xnm, g_qnm, g_zm, qb);
    else
        ftc<96>(sm, g_Xvh, g_Xvl, g_xqv, g_Lth1, g_Ltl1, g_Xnv, g_qnv, g_zv, qb);
}

// -------------------- combine ----------------------------------------------
__global__ void combine_kernel(const float* __restrict__ y_mean,
                               const float* __restrict__ y_var,
                               float* __restrict__ out) {
    int i = blockIdx.x * blockDim.x + threadIdx.x;
    if (i < N * 32)
        out[i] = (y_mean[i] + g_zm[i]) + (y_var[i] + g_zv[i]);
}

// -------------------- launch ------------------------------------------------
extern "C" void kernel_launch(void* const* d_in, const int* in_sizes, int n_in,
                              void* d_out, int out_size) {
    const float* x_mu   = (const float*)d_in[0];
    const float* y_eta  = (const float*)d_in[1];
    const float* y_mean = (const float*)d_in[2];
    const float* y_var  = (const float*)d_in[3];
    const float* X_mean = (const float*)d_in[4];
    const float* X_var  = (const float*)d_in[5];
    const float* Z_mean = (const float*)d_in[6];
    const float* Z_var  = (const float*)d_in[7];
    const float* kMi    = (const float*)d_in[8];
    const float* kVi    = (const float*)d_in[9];
    float* out = (float*)d_out;

    cudaFuncSetAttribute(fusedtc_kernel,
                         cudaFuncAttributeMaxDynamicSharedMemorySize, FUSED_SMEM);

    prep_q_kernel<<<(N * 32 + 255) / 256, 256>>>(x_mu, y_eta, y_mean, y_var);
    prep_X_kernel<<<(N * 32 + 255) / 256, 256>>>(X_mean, X_var);
    lambda_gemm_kernel<<<dim3(N / 64, 2), 256>>>(kMi, Z_mean, kVi, Z_var);
    lsplit_kernel<<<(2 * 32 * N + 255) / 256, 256>>>();
    fusedtc_kernel<<<128, 256, FUSED_SMEM>>>();
    combine_kernel<<<(N * 32 + 255) / 256, 256>>>(y_mean, y_var, out);
}

// round 7
// speedup vs baseline: 8.2048x; 2.0921x over previous
#include <cuda_runtime.h>
#include <cuda_bf16.h>
#include <cstdint>

#define N 8192

// -------------------- device scratch ---------------------------------------
__device__ float g_xqm[N * 64];
__device__ float g_xqv[N * 96];
__device__ float g_qnm[N], g_qnv[N], g_Xnm[N], g_Xnv[N];
__device__ float g_LpA0[N * 32], g_LpB0[N * 32];   // Lambda partials (k-halves)
__device__ float g_LpA1[N * 32], g_LpB1[N * 32];
__device__ float g_zm[N * 32], g_zv[N * 32];
__device__ __align__(16) __nv_bfloat16 g_Xmh[N * 64], g_Xml[N * 64];
__device__ __align__(16) __nv_bfloat16 g_Xvh[N * 96], g_Xvl[N * 96];
__device__ __align__(16) __nv_bfloat16 g_Lth0[32 * N], g_Ltl0[32 * N];
__device__ __align__(16) __nv_bfloat16 g_Lth1[32 * N], g_Ltl1[32 * N];
__device__ __align__(16) __nv_bfloat16 g_Zth0[32 * N], g_Ztl0[32 * N];
__device__ __align__(16) __nv_bfloat16 g_Zth1[32 * N], g_Ztl1[32 * N];

// -------------------- mma helpers (sm_80+ HMMA) -----------------------------
__device__ __forceinline__ void mma_bf16(float c[4], const uint32_t a[4],
                                         uint32_t b0, uint32_t b1) {
    asm volatile(
        "mma.sync.aligned.m16n8k16.row.col.f32.bf16.bf16.f32 "
        "{%0,%1,%2,%3}, {%4,%5,%6,%7}, {%8,%9}, {%0,%1,%2,%3};"
        : "+f"(c[0]), "+f"(c[1]), "+f"(c[2]), "+f"(c[3])
        : "r"(a[0]), "r"(a[1]), "r"(a[2]), "r"(a[3]), "r"(b0), "r"(b1));
}
__device__ __forceinline__ uint32_t packbf(float lo, float hi) {
    uint32_t r;
    asm("cvt.rn.bf16x2.f32 %0, %1, %2;" : "=r"(r) : "f"(hi), "f"(lo));
    return r;
}
__device__ __forceinline__ uint32_t ldsw(const __nv_bfloat16* p) {
    return *(const uint32_t*)p;
}

// -------------------- prep kernels ------------------------------------------
__global__ void prep_q_kernel(const float* __restrict__ x_mu,
                              const float* __restrict__ y_eta,
                              const float* __restrict__ y_mean,
                              const float* __restrict__ y_var) {
    int q = (blockIdx.x * blockDim.x + threadIdx.x) >> 5;
    int lane = threadIdx.x & 31;
    if (q >= N) return;
    float a = x_mu[q * 32 + lane];
    float m = y_mean[q * 32 + lane] + y_var[q * 32 + lane];
    float e = 0.01f * y_eta[(N - 1 - q) * 32 + lane];
    g_xqm[q * 64 + lane] = a;       g_xqm[q * 64 + 32 + lane] = m;
    g_xqv[q * 96 + lane] = a;       g_xqv[q * 96 + 32 + lane] = e;
    g_xqv[q * 96 + 64 + lane] = m;
    float nm = a * a + m * m, nv = nm + e * e;
    #pragma unroll
    for (int o = 16; o; o >>= 1) {
        nm += __shfl_xor_sync(0xffffffffu, nm, o);
        nv += __shfl_xor_sync(0xffffffffu, nv, o);
    }
    if (lane == 0) { g_qnm[q] = nm; g_qnv[q] = nv; }
}

__global__ void prep_X_kernel(const float* __restrict__ Xm,
                              const float* __restrict__ Xv) {
    int i = (blockIdx.x * blockDim.x + threadIdx.x) >> 5;
    int lane = threadIdx.x & 31;
    if (i >= N) return;
    float nm = 0.f, nv = 0.f;
    #pragma unroll
    for (int c = 0; c < 64; c += 32) {
        float v = Xm[(size_t)i * 64 + c + lane];
        nm += v * v;
        __nv_bfloat16 h = __float2bfloat16(v);
        g_Xmh[(size_t)i * 64 + c + lane] = h;
        g_Xml[(size_t)i * 64 + c + lane] = __float2bfloat16(v - __bfloat162float(h));
    }
    #pragma unroll
    for (int c = 0; c < 96; c += 32) {
        float v = Xv[(size_t)i * 96 + c + lane];
        nv += v * v;
        __nv_bfloat16 h = __float2bfloat16(v);
        g_Xvh[(size_t)i * 96 + c + lane] = h;
        g_Xvl[(size_t)i * 96 + c + lane] = __float2bfloat16(v - __bfloat162float(h));
    }
    #pragma unroll
    for (int o = 16; o; o >>= 1) {
        nm += __shfl_xor_sync(0xffffffffu, nm, o);
        nv += __shfl_xor_sync(0xffffffffu, nv, o);
    }
    if (lane == 0) { g_Xnm[i] = nm; g_Xnv[i] = nv; }
}

// Z -> transposed bf16 hi/lo [32][N]
__global__ void zsplit_kernel(const float* __restrict__ Z0,
                              const float* __restrict__ Z1) {
    int idx = blockIdx.x * blockDim.x + threadIdx.x;
    if (idx >= 2 * 32 * N) return;
    int t = idx >= 32 * N;
    int j = idx - t * 32 * N;
    int n = j / N, k = j - n * N;
    float v = (t ? Z1 : Z0)[(size_t)k * 32 + n];
    __nv_bfloat16 h = __float2bfloat16(v);
    (t ? g_Zth1 : g_Zth0)[j] = h;
    (t ? g_Ztl1 : g_Ztl0)[j] = __float2bfloat16(v - __bfloat162float(h));
}

// -------------------- Lambda = kXX_inv @ Z on HMMA --------------------------
// grid (64, task, khalf): 128 rows per CTA, k-range split in half.
// Per chunk (k64): stage A fp32->bf16 hi/lo SMEM + Zt chunk, then
// warp w does rows [16w,16w+16) x 32 cols via 4 kt x 4 nt x 3 MMA.
__global__ __launch_bounds__(256, 2) void lambda_hmma_kernel(
    const float* __restrict__ A0, const float* __restrict__ A1) {
    const int task = blockIdx.y, kh = blockIdx.z;
    const float* A = task ? A1 : A0;
    const __nv_bfloat16* Zh = task ? g_Zth1 : g_Zth0;
    const __nv_bfloat16* Zl = task ? g_Ztl1 : g_Ztl0;
    float* Lp = task ? (kh ? g_LpB1 : g_LpA1) : (kh ? g_LpB0 : g_LpA0);

    __shared__ __align__(16) uint32_t sAh[128 * 36], sAl[128 * 36];
    __shared__ __align__(16) uint32_t sZh[32 * 36], sZl[32 * 36];

    const int tid = threadIdx.x, lane = tid & 31, w = tid >> 5;
    const int t = lane & 3, qr = lane >> 2;
    const int rb = blockIdx.x * 128;
    const int kb0 = kh * (N / 2);
    const int zn = (tid * 4) >> 5, zw4 = (tid * 4) & 31;

    float4 pa[8];
    uint4 pzh, pzl;
    // prefetch chunk 0
    #pragma unroll
    for (int it = 0; it < 8; it++) {
        int idx = tid + it * 256;
        int r = idx >> 4, c4 = idx & 15;
        pa[it] = *(const float4*)&A[(size_t)(rb + r) * N + kb0 + c4 * 4];
    }
    pzh = ((const uint4*)Zh)[(zn * (N / 2) + kb0 / 2 + zw4) >> 2];
    pzl = ((const uint4*)Zl)[(zn * (N / 2) + kb0 / 2 + zw4) >> 2];

    float zc[4][4];
    #pragma unroll
    for (int i = 0; i < 4; i++)
        #pragma unroll
        for (int j = 0; j < 4; j++) zc[i][j] = 0.f;

    for (int cb = 0; cb < 64; cb++) {
        __syncthreads();
        // store staged chunk (convert A fp32 -> bf16 hi/lo)
        #pragma unroll
        for (int it = 0; it < 8; it++) {
            int idx = tid + it * 256;
            int r = idx >> 4, c4 = idx & 15;
            float4 v = pa[it];
            uint32_t h0 = packbf(v.x, v.y);
            uint32_t h1 = packbf(v.z, v.w);
            float r0 = v.x - __uint_as_float(h0 << 16);
            float r1 = v.y - __uint_as_float(h0 & 0xffff0000u);
            float r2 = v.z - __uint_as_float(h1 << 16);
            float r3 = v.w - __uint_as_float(h1 & 0xffff0000u);
            *(uint2*)&sAh[r * 36 + c4 * 2] = make_uint2(h0, h1);
            *(uint2*)&sAl[r * 36 + c4 * 2] = make_uint2(packbf(r0, r1), packbf(r2, r3));
        }
        *(uint4*)&sZh[zn * 36 + zw4] = pzh;
        *(uint4*)&sZl[zn * 36 + zw4] = pzl;
        __syncthreads();

        if (cb < 63) {  // prefetch next chunk while MMAs run
            const int ko = kb0 + (cb + 1) * 64;
            #pragma unroll
            for (int it = 0; it < 8; it++) {
                int idx = tid + it * 256;
                int r = idx >> 4, c4 = idx & 15;
                pa[it] = *(const float4*)&A[(size_t)(rb + r) * N + ko + c4 * 4];
            }
            pzh = ((const uint4*)Zh)[(zn * (N / 2) + ko / 2 + zw4) >> 2];
            pzl = ((const uint4*)Zl)[(zn * (N / 2) + ko / 2 + zw4) >> 2];
        }

        #pragma unroll
        for (int kt = 0; kt < 4; kt++) {
            const int kw = kt * 8 + t;
            uint32_t ah[4], al[4];
            ah[0] = sAh[(w * 16 + qr) * 36 + kw];
            ah[1] = sAh[(w * 16 + qr + 8) * 36 + kw];
            ah[2] = sAh[(w * 16 + qr) * 36 + kw + 4];
            ah[3] = sAh[(w * 16 + qr + 8) * 36 + kw + 4];
            al[0] = sAl[(w * 16 + qr) * 36 + kw];
            al[1] = sAl[(w * 16 + qr + 8) * 36 + kw];
            al[2] = sAl[(w * 16 + qr) * 36 + kw + 4];
            al[3] = sAl[(w * 16 + qr + 8) * 36 + kw + 4];
            #pragma unroll
            for (int nt = 0; nt < 4; nt++) {
                const int nc = nt * 8 + qr;
                uint32_t bh0 = sZh[nc * 36 + kw], bh1 = sZh[nc * 36 + kw + 4];
                uint32_t bl0 = sZl[nc * 36 + kw], bl1 = sZl[nc * 36 + kw + 4];
                mma_bf16(zc[nt], ah, bh0, bh1);
                mma_bf16(zc[nt], ah, bl0, bl1);
                mma_bf16(zc[nt], al, bh0, bh1);
            }
        }
    }

    const int row0 = rb + w * 16 + qr;
    #pragma unroll
    for (int nt = 0; nt < 4; nt++) {
        const int col = nt * 8 + 2 * t;
        Lp[(size_t)row0 * 32 + col]           = zc[nt][0];
        Lp[(size_t)row0 * 32 + col + 1]       = zc[nt][1];
        Lp[(size_t)(row0 + 8) * 32 + col]     = zc[nt][2];
        Lp[(size_t)(row0 + 8) * 32 + col + 1] = zc[nt][3];
    }
}

// Lambda partial sums -> transposed bf16 hi/lo [32][N]
__global__ void lsplit_kernel() {
    int idx = blockIdx.x * blockDim.x + threadIdx.x;
    if (idx >= 2 * 32 * N) return;
    int t = idx >= 32 * N;
    int j = idx - t * 32 * N;
    int n = j / N, k = j - n * N;
    size_t src = (size_t)k * 32 + n;
    float v = (t ? g_LpA1 : g_LpA0)[src] + (t ? g_LpB1 : g_LpB0)[src];
    __nv_bfloat16 h = __float2bfloat16(v);
    (t ? g_Lth1 : g_Lth0)[j] = h;
    (t ? g_Ltl1 : g_Ltl0)[j] = __float2bfloat16(v - __bfloat162float(h));
}

// -------------------- fused HMMA kernel (512 thr, x-split warpgroups) -------
template <int D>
__device__ void ftc(char* smraw, const __nv_bfloat16* Xh, const __nv_bfloat16* Xl,
                    const float* Qg, const __nv_bfloat16* Lth,
                    const __nv_bfloat16* Ltl, const float* Xn,
                    const float* Qn, float* Zg, int qb) {
    constexpr int QS = D + 8;
    __nv_bfloat16* sQh  = (__nv_bfloat16*)smraw;
    __nv_bfloat16* sQl  = sQh + 128 * QS;
    __nv_bfloat16* sXhB = sQl + 128 * QS;
    __nv_bfloat16* sXlB = sXhB + 2 * 64 * QS;
    __nv_bfloat16* sLhB = sXlB + 2 * 64 * QS;
    __nv_bfloat16* sLlB = sLhB + 2 * 32 * 72;
    float* sXnB = (float*)(sLlB + 2 * 32 * 72);
    float* sRed = (float*)sXhB;            // reused after the chunk loop

    const int tid = threadIdx.x;
    const int g = tid >> 8, wtid = tid & 255;
    const int lane = tid & 31, w = wtid >> 5;
    const int t = lane & 3, qr = lane >> 2;
    const int wq0 = w * 16;
    __nv_bfloat16* sXh = sXhB + g * 64 * QS;
    __nv_bfloat16* sXl = sXlB + g * 64 * QS;
    __nv_bfloat16* sLh = sLhB + g * 32 * 72;
    __nv_bfloat16* sLl = sLlB + g * 32 * 72;
    float* sXn = sXnB + g * 64;

    // split Q -> SMEM bf16 hi/lo (all 512 threads)
    for (int i = tid; i < 128 * D; i += 512) {
        int r = i / D, c = i - r * D;
        float v = Qg[(size_t)(qb + r) * D + c];
        __nv_bfloat16 h = __float2bfloat16(v);
        sQh[r * QS + c] = h;
        sQl[r * QS + c] = __float2bfloat16(v - __bfloat162float(h));
    }
    const float qn0 = Qn[qb + wq0 + qr];
    const float qn1 = Qn[qb + wq0 + qr + 8];

    float zc[4][4];
    #pragma unroll
    for (int i = 0; i < 4; i++)
        #pragma unroll
        for (int j = 0; j < 4; j++) zc[i][j] = 0.f;

    for (int it = 0; it < 64; it++) {
        const int xb = (2 * it + g) * 64;
        // ---- stage this group's chunk ----
        #pragma unroll
        for (int i = wtid; i < 64 * (D / 4); i += 256) {
            int r = i / (D / 4), p = i - r * (D / 4);
            uint2 vh = ((const uint2*)Xh)[(size_t)(xb + r) * (D / 4) + p];
            uint2 vl = ((const uint2*)Xl)[(size_t)(xb + r) * (D / 4) + p];
            *(uint2*)(sXh + r * QS + p * 4) = vh;
            *(uint2*)(sXl + r * QS + p * 4) = vl;
        }
        #pragma unroll
        for (int i = wtid; i < 32 * 16; i += 256) {
            int n = i >> 4, p = i & 15;
            uint2 vh = ((const uint2*)Lth)[(size_t)n * (N / 4) + xb / 4 + p];
            uint2 vl = ((const uint2*)Ltl)[(size_t)n * (N / 4) + xb / 4 + p];
            *(uint2*)(sLh + n * 72 + p * 4) = vh;
            *(uint2*)(sLl + n * 72 + p * 4) = vl;
        }
        if (wtid < 64) sXn[wtid] = Xn[xb + wtid];
        __syncthreads();

        // ---- phase 1: D1[16q x 64x] ----
        float c1[8][4];
        #pragma unroll
        for (int i = 0; i < 8; i++)
            #pragma unroll
            for (int j = 0; j < 4; j++) c1[i][j] = 0.f;

        #pragma unroll
        for (int kt = 0; kt < D / 16; kt++) {
            const int k0 = kt * 16 + 2 * t;
            uint32_t ah[4], al[4];
            ah[0] = ldsw(sQh + (wq0 + qr) * QS + k0);
            ah[1] = ldsw(sQh + (wq0 + qr + 8) * QS + k0);
            ah[2] = ldsw(sQh + (wq0 + qr) * QS + k0 + 8);
            ah[3] = ldsw(sQh + (wq0 + qr + 8) * QS + k0 + 8);
            al[0] = ldsw(sQl + (wq0 + qr) * QS + k0);
            al[1] = ldsw(sQl + (wq0 + qr + 8) * QS + k0);
            al[2] = ldsw(sQl + (wq0 + qr) * QS + k0 + 8);
            al[3] = ldsw(sQl + (wq0 + qr + 8) * QS + k0 + 8);
            #pragma unroll
            for (int nt = 0; nt < 8; nt++) {
                const int xr = nt * 8 + qr;
                uint32_t bh0 = ldsw(sXh + xr * QS + k0);
                uint32_t bh1 = ldsw(sXh + xr * QS + k0 + 8);
                uint32_t bl0 = ldsw(sXl + xr * QS + k0);
                uint32_t bl1 = ldsw(sXl + xr * QS + k0 + 8);
                mma_bf16(c1[nt], ah, bh0, bh1);
                mma_bf16(c1[nt], ah, bl0, bl1);
                mma_bf16(c1[nt], al, bh0, bh1);
            }
        }

        // ---- epilogue: exp -> P fragments (C m16n8 -> A m16k16 repack) ----
        uint32_t Ph[4][4], Pl[4][4];
        #pragma unroll
        for (int kt2 = 0; kt2 < 4; kt2++) {
            #pragma unroll
            for (int s = 0; s < 2; s++) {
                const int nt = 2 * kt2 + s;
                const int x0 = nt * 8 + 2 * t;
                float xna = sXn[x0], xnb = sXn[x0 + 1];
                float p0 = __expf(-0.0078125f * fmaxf(qn0 + xna - 2.f * c1[nt][0], 0.f));
                float p1 = __expf(-0.0078125f * fmaxf(qn0 + xnb - 2.f * c1[nt][1], 0.f));
                float p2 = __expf(-0.0078125f * fmaxf(qn1 + xna - 2.f * c1[nt][2], 0.f));
                float p3 = __expf(-0.0078125f * fmaxf(qn1 + xnb - 2.f * c1[nt][3], 0.f));
                uint32_t w0 = packbf(p0, p1);
                uint32_t w1 = packbf(p2, p3);
                float r0 = p0 - __uint_as_float(w0 << 16);
                float r1 = p1 - __uint_as_float(w0 & 0xffff0000u);
                float r2 = p2 - __uint_as_float(w1 << 16);
                float r3 = p3 - __uint_as_float(w1 & 0xffff0000u);
                Ph[kt2][2 * s]     = w0;
                Ph[kt2][2 * s + 1] = w1;
                Pl[kt2][2 * s]     = packbf(r0, r1);
                Pl[kt2][2 * s + 1] = packbf(r2, r3);
            }
        }

        // ---- phase 2: z += P . Lambda^T ----
        #pragma unroll
        for (int kt2 = 0; kt2 < 4; kt2++) {
            const int k0 = kt2 * 16 + 2 * t;
            #pragma unroll
            for (int nt = 0; nt < 4; nt++) {
                const int nc = nt * 8 + qr;
                uint32_t bh0 = ldsw(sLh + nc * 72 + k0);
                uint32_t bh1 = ldsw(sLh + nc * 72 + k0 + 8);
                uint32_t bl0 = ldsw(sLl + nc * 72 + k0);
                uint32_t bl1 = ldsw(sLl + nc * 72 + k0 + 8);
                mma_bf16(zc[nt], Ph[kt2], bh0, bh1);
                mma_bf16(zc[nt], Ph[kt2], bl0, bl1);
                mma_bf16(zc[nt], Pl[kt2], bh0, bh1);
            }
        }
        __syncthreads();
    }

    // ---- combine the two x-half partial sums ----
    const int row0 = wq0 + qr;
    if (g == 1) {
        #pragma unroll
        for (int nt = 0; nt < 4; nt++) {
            const int col = nt * 8 + 2 * t;
            sRed[row0 * 33 + col]           = zc[nt][0];
            sRed[row0 * 33 + col + 1]       = zc[nt][1];
            sRed[(row0 + 8) * 33 + col]     = zc[nt][2];
            sRed[(row0 + 8) * 33 + col + 1] = zc[nt][3];
        }
    }
    __syncthreads();
    if (g == 0) {
        #pragma unroll
        for (int nt = 0; nt < 4; nt++) {
            const int col = nt * 8 + 2 * t;
            float v0 = zc[nt][0] + sRed[row0 * 33 + col];
            float v1 = zc[nt][1] + sRed[row0 * 33 + col + 1];
            float v2 = zc[nt][2] + sRed[(row0 + 8) * 33 + col];
            float v3 = zc[nt][3] + sRed[(row0 + 8) * 33 + col + 1];
            Zg[(size_t)(qb + row0) * 32 + col]           = v0;
            Zg[(size_t)(qb + row0) * 32 + col + 1]       = v1;
            Zg[(size_t)(qb + row0 + 8) * 32 + col]       = v2;
            Zg[(size_t)(qb + row0 + 8) * 32 + col + 1]   = v3;
        }
    }
}

// D=96: (2*128*104 + 2*2*64*104 + 2*2*32*72) bf16 + 2*64 f32 = 125440 B
#define FUSED_SMEM 126464

__global__ __launch_bounds__(512, 1) void fusedtc_kernel() {
    extern __shared__ char sm[];
    int task = blockIdx.x >> 6;
    int qb   = (blockIdx.x & 63) * 128;
    if (task == 0)
        ftc<64>(sm, g_Xmh, g_Xml, g_xqm, g_Lth0, g_Ltl0, g_Xnm, g_qnm, g_zm, qb);
    else
        ftc<96>(sm, g_Xvh, g_Xvl, g_xqv, g_Lth1, g_Ltl1, g_Xnv, g_qnv, g_zv, qb);
}

// -------------------- combine ----------------------------------------------
__global__ void combine_kernel(const float* __restrict__ y_mean,
                               const float* __restrict__ y_var,
                               float* __restrict__ out) {
    int i = blockIdx.x * blockDim.x + threadIdx.x;
    if (i < N * 32)
        out[i] = (y_mean[i] + g_zm[i]) + (y_var[i] + g_zv[i]);
}

// -------------------- launch ------------------------------------------------
extern "C" void kernel_launch(void* const* d_in, const int* in_sizes, int n_in,
                              void* d_out, int out_size) {
    const float* x_mu   = (const float*)d_in[0];
    const float* y_eta  = (const float*)d_in[1];
    const float* y_mean = (const float*)d_in[2];
    const float* y_var  = (const float*)d_in[3];
    const float* X_mean = (const float*)d_in[4];
    const float* X_var  = (const float*)d_in[5];
    const float* Z_mean = (const float*)d_in[6];
    const float* Z_var  = (const float*)d_in[7];
    const float* kMi    = (const float*)d_in[8];
    const float* kVi    = (const float*)d_in[9];
    float* out = (float*)d_out;

    cudaFuncSetAttribute(fusedtc_kernel,
                         cudaFuncAttributeMaxDynamicSharedMemorySize, FUSED_SMEM);

    prep_q_kernel<<<(N * 32 + 255) / 256, 256>>>(x_mu, y_eta, y_mean, y_var);
    prep_X_kernel<<<(N * 32 + 255) / 256, 256>>>(X_mean, X_var);
    zsplit_kernel<<<(2 * 32 * N + 255) / 256, 256>>>(Z_mean, Z_var);
    lambda_hmma_kernel<<<dim3(64, 2, 2), 256>>>(kMi, kVi);
    lsplit_kernel<<<(2 * 32 * N + 255) / 256, 256>>>();
    fusedtc_kernel<<<128, 512, FUSED_SMEM>>>();
    combine_kernel<<<(N * 32 + 255) / 256, 256>>>(y_mean, y_var, out);
}

// round 8
// speedup vs baseline: 9.6423x; 1.1752x over previous
#include <cuda_runtime.h>
#include <cuda_fp16.h>
#include <cstdint>

#define N 8192

// -------------------- device scratch ---------------------------------------
__device__ float g_xqm[N * 64];
__device__ float g_xqv[N * 96];
__device__ float g_qnm[N], g_qnv[N], g_Xnm[N], g_Xnv[N];
__device__ float g_LpA0[N * 32], g_LpB0[N * 32];   // Lambda partials (k-halves)
__device__ float g_LpA1[N * 32], g_LpB1[N * 32];
__device__ float g_zm[N * 32], g_zv[N * 32];
__device__ __align__(16) __half g_Xmh[N * 64];          // X hi only (phase1 2-MMA)
__device__ __align__(16) __half g_Xvh[N * 96];
__device__ __align__(16) __half g_Lth0[32 * N], g_Ltl0[32 * N];
__device__ __align__(16) __half g_Lth1[32 * N], g_Ltl1[32 * N];
__device__ __align__(16) __half g_Zth0[32 * N], g_Ztl0[32 * N];
__device__ __align__(16) __half g_Zth1[32 * N], g_Ztl1[32 * N];

// -------------------- mma helpers (sm_80+ HMMA fp16) ------------------------
__device__ __forceinline__ void mma_f16(float c[4], const uint32_t a[4],
                                        uint32_t b0, uint32_t b1) {
    asm volatile(
        "mma.sync.aligned.m16n8k16.row.col.f32.f16.f16.f32 "
        "{%0,%1,%2,%3}, {%4,%5,%6,%7}, {%8,%9}, {%0,%1,%2,%3};"
        : "+f"(c[0]), "+f"(c[1]), "+f"(c[2]), "+f"(c[3])
        : "r"(a[0]), "r"(a[1]), "r"(a[2]), "r"(a[3]), "r"(b0), "r"(b1));
}
__device__ __forceinline__ uint32_t packhf(float lo, float hi) {
    uint32_t r;
    asm("cvt.rn.f16x2.f32 %0, %1, %2;" : "=r"(r) : "f"(hi), "f"(lo));
    return r;
}
__device__ __forceinline__ float2 up2(uint32_t w) {
    __half2 h = *reinterpret_cast<__half2*>(&w);
    return __half22float2(h);
}
__device__ __forceinline__ uint32_t ldsw(const __half* p) {
    return *(const uint32_t*)p;
}

// -------------------- prep kernels ------------------------------------------
__global__ void prep_q_kernel(const float* __restrict__ x_mu,
                              const float* __restrict__ y_eta,
                              const float* __restrict__ y_mean,
                              const float* __restrict__ y_var) {
    int q = (blockIdx.x * blockDim.x + threadIdx.x) >> 5;
    int lane = threadIdx.x & 31;
    if (q >= N) return;
    float a = x_mu[q * 32 + lane];
    float m = y_mean[q * 32 + lane] + y_var[q * 32 + lane];
    float e = 0.01f * y_eta[(N - 1 - q) * 32 + lane];
    g_xqm[q * 64 + lane] = a;       g_xqm[q * 64 + 32 + lane] = m;
    g_xqv[q * 96 + lane] = a;       g_xqv[q * 96 + 32 + lane] = e;
    g_xqv[q * 96 + 64 + lane] = m;
    float nm = a * a + m * m, nv = nm + e * e;
    #pragma unroll
    for (int o = 16; o; o >>= 1) {
        nm += __shfl_xor_sync(0xffffffffu, nm, o);
        nv += __shfl_xor_sync(0xffffffffu, nv, o);
    }
    if (lane == 0) { g_qnm[q] = nm; g_qnv[q] = nv; }
}

__global__ void prep_X_kernel(const float* __restrict__ Xm,
                              const float* __restrict__ Xv) {
    int i = (blockIdx.x * blockDim.x + threadIdx.x) >> 5;
    int lane = threadIdx.x & 31;
    if (i >= N) return;
    float nm = 0.f, nv = 0.f;
    #pragma unroll
    for (int c = 0; c < 64; c += 32) {
        float v = Xm[(size_t)i * 64 + c + lane];
        nm += v * v;
        g_Xmh[(size_t)i * 64 + c + lane] = __float2half_rn(v);
    }
    #pragma unroll
    for (int c = 0; c < 96; c += 32) {
        float v = Xv[(size_t)i * 96 + c + lane];
        nv += v * v;
        g_Xvh[(size_t)i * 96 + c + lane] = __float2half_rn(v);
    }
    #pragma unroll
    for (int o = 16; o; o >>= 1) {
        nm += __shfl_xor_sync(0xffffffffu, nm, o);
        nv += __shfl_xor_sync(0xffffffffu, nv, o);
    }
    if (lane == 0) { g_Xnm[i] = nm; g_Xnv[i] = nv; }
}

// Z -> transposed fp16 hi/lo [32][N]
__global__ void zsplit_kernel(const float* __restrict__ Z0,
                              const float* __restrict__ Z1) {
    int idx = blockIdx.x * blockDim.x + threadIdx.x;
    if (idx >= 2 * 32 * N) return;
    int t = idx >= 32 * N;
    int j = idx - t * 32 * N;
    int n = j / N, k = j - n * N;
    float v = (t ? Z1 : Z0)[(size_t)k * 32 + n];
    __half h = __float2half_rn(v);
    (t ? g_Zth1 : g_Zth0)[j] = h;
    (t ? g_Ztl1 : g_Ztl0)[j] = __float2half_rn(v - __half2float(h));
}

// -------------------- Lambda = kXX_inv @ Z on HMMA (fp16 hi/lo, 3-MMA) ------
__global__ __launch_bounds__(256, 2) void lambda_hmma_kernel(
    const float* __restrict__ A0, const float* __restrict__ A1) {
    const int task = blockIdx.y, kh = blockIdx.z;
    const float* A = task ? A1 : A0;
    const __half* Zh = task ? g_Zth1 : g_Zth0;
    const __half* Zl = task ? g_Ztl1 : g_Ztl0;
    float* Lp = task ? (kh ? g_LpB1 : g_LpA1) : (kh ? g_LpB0 : g_LpA0);

    __shared__ __align__(16) uint32_t sAh[128 * 36], sAl[128 * 36];
    __shared__ __align__(16) uint32_t sZh[32 * 36], sZl[32 * 36];

    const int tid = threadIdx.x, lane = tid & 31, w = tid >> 5;
    const int t = lane & 3, qr = lane >> 2;
    const int rb = blockIdx.x * 128;
    const int kb0 = kh * (N / 2);
    const int zn = (tid * 4) >> 5, zw4 = (tid * 4) & 31;

    float4 pa[8];
    uint4 pzh, pzl;
    #pragma unroll
    for (int it = 0; it < 8; it++) {
        int idx = tid + it * 256;
        int r = idx >> 4, c4 = idx & 15;
        pa[it] = *(const float4*)&A[(size_t)(rb + r) * N + kb0 + c4 * 4];
    }
    pzh = ((const uint4*)Zh)[(zn * (N / 2) + kb0 / 2 + zw4) >> 2];
    pzl = ((const uint4*)Zl)[(zn * (N / 2) + kb0 / 2 + zw4) >> 2];

    float zc[4][4];
    #pragma unroll
    for (int i = 0; i < 4; i++)
        #pragma unroll
        for (int j = 0; j < 4; j++) zc[i][j] = 0.f;

    for (int cb = 0; cb < 64; cb++) {
        __syncthreads();
        #pragma unroll
        for (int it = 0; it < 8; it++) {
            int idx = tid + it * 256;
            int r = idx >> 4, c4 = idx & 15;
            float4 v = pa[it];
            uint32_t h0 = packhf(v.x, v.y);
            uint32_t h1 = packhf(v.z, v.w);
            float2 f0 = up2(h0), f1 = up2(h1);
            *(uint2*)&sAh[r * 36 + c4 * 2] = make_uint2(h0, h1);
            *(uint2*)&sAl[r * 36 + c4 * 2] =
                make_uint2(packhf(v.x - f0.x, v.y - f0.y),
                           packhf(v.z - f1.x, v.w - f1.y));
        }
        *(uint4*)&sZh[zn * 36 + zw4] = pzh;
        *(uint4*)&sZl[zn * 36 + zw4] = pzl;
        __syncthreads();

        if (cb < 63) {
            const int ko = kb0 + (cb + 1) * 64;
            #pragma unroll
            for (int it = 0; it < 8; it++) {
                int idx = tid + it * 256;
                int r = idx >> 4, c4 = idx & 15;
                pa[it] = *(const float4*)&A[(size_t)(rb + r) * N + ko + c4 * 4];
            }
            pzh = ((const uint4*)Zh)[(zn * (N / 2) + ko / 2 + zw4) >> 2];
            pzl = ((const uint4*)Zl)[(zn * (N / 2) + ko / 2 + zw4) >> 2];
        }

        #pragma unroll
        for (int kt = 0; kt < 4; kt++) {
            const int kw = kt * 8 + t;
            uint32_t ah[4], al[4];
            ah[0] = sAh[(w * 16 + qr) * 36 + kw];
            ah[1] = sAh[(w * 16 + qr + 8) * 36 + kw];
            ah[2] = sAh[(w * 16 + qr) * 36 + kw + 4];
            ah[3] = sAh[(w * 16 + qr + 8) * 36 + kw + 4];
            al[0] = sAl[(w * 16 + qr) * 36 + kw];
            al[1] = sAl[(w * 16 + qr + 8) * 36 + kw];
            al[2] = sAl[(w * 16 + qr) * 36 + kw + 4];
            al[3] = sAl[(w * 16 + qr + 8) * 36 + kw + 4];
            #pragma unroll
            for (int nt = 0; nt < 4; nt++) {
                const int nc = nt * 8 + qr;
                uint32_t bh0 = sZh[nc * 36 + kw], bh1 = sZh[nc * 36 + kw + 4];
                uint32_t bl0 = sZl[nc * 36 + kw], bl1 = sZl[nc * 36 + kw + 4];
                mma_f16(zc[nt], ah, bh0, bh1);
                mma_f16(zc[nt], ah, bl0, bl1);
                mma_f16(zc[nt], al, bh0, bh1);
            }
        }
    }

    const int row0 = rb + w * 16 + qr;
    #pragma unroll
    for (int nt = 0; nt < 4; nt++) {
        const int col = nt * 8 + 2 * t;
        Lp[(size_t)row0 * 32 + col]           = zc[nt][0];
        Lp[(size_t)row0 * 32 + col + 1]       = zc[nt][1];
        Lp[(size_t)(row0 + 8) * 32 + col]     = zc[nt][2];
        Lp[(size_t)(row0 + 8) * 32 + col + 1] = zc[nt][3];
    }
}

// Lambda partial sums -> transposed fp16 hi/lo [32][N]
__global__ void lsplit_kernel() {
    int idx = blockIdx.x * blockDim.x + threadIdx.x;
    if (idx >= 2 * 32 * N) return;
    int t = idx >= 32 * N;
    int j = idx - t * 32 * N;
    int n = j / N, k = j - n * N;
    size_t src = (size_t)k * 32 + n;
    float v = (t ? g_LpA1 : g_LpA0)[src] + (t ? g_LpB1 : g_LpB0)[src];
    __half h = __float2half_rn(v);
    (t ? g_Lth1 : g_Lth0)[j] = h;
    (t ? g_Ltl1 : g_Ltl0)[j] = __float2half_rn(v - __half2float(h));
}

// -------------------- fused HMMA kernel (fp16; phase1 2-MMA) ----------------
template <int D>
__device__ void ftc(char* smraw, const __half* Xh,
                    const float* Qg, const __half* Lth,
                    const __half* Ltl, const float* Xn,
                    const float* Qn, float* Zg, int qb) {
    constexpr int QS = D + 8;
    __half* sQh  = (__half*)smraw;
    __half* sQl  = sQh + 128 * QS;
    __half* sXhB = sQl + 128 * QS;
    __half* sLhB = sXhB + 2 * 64 * QS;
    __half* sLlB = sLhB + 2 * 32 * 72;
    float* sXnB = (float*)(sLlB + 2 * 32 * 72);
    float* sRed = (float*)sXhB;            // reused after the chunk loop

    const int tid = threadIdx.x;
    const int g = tid >> 8, wtid = tid & 255;
    const int lane = tid & 31, w = wtid >> 5;
    const int t = lane & 3, qr = lane >> 2;
    const int wq0 = w * 16;
    __half* sXh = sXhB + g * 64 * QS;
    __half* sLh = sLhB + g * 32 * 72;
    __half* sLl = sLlB + g * 32 * 72;
    float* sXn = sXnB + g * 64;

    // split Q -> SMEM fp16 hi/lo (all 512 threads)
    for (int i = tid; i < 128 * D; i += 512) {
        int r = i / D, c = i - r * D;
        float v = Qg[(size_t)(qb + r) * D + c];
        __half h = __float2half_rn(v);
        sQh[r * QS + c] = h;
        sQl[r * QS + c] = __float2half_rn(v - __half2float(h));
    }
    const float qn0 = Qn[qb + wq0 + qr];
    const float qn1 = Qn[qb + wq0 + qr + 8];

    float zc[4][4];
    #pragma unroll
    for (int i = 0; i < 4; i++)
        #pragma unroll
        for (int j = 0; j < 4; j++) zc[i][j] = 0.f;

    for (int it = 0; it < 64; it++) {
        const int xb = (2 * it + g) * 64;
        // ---- stage this group's chunk ----
        #pragma unroll
        for (int i = wtid; i < 64 * (D / 4); i += 256) {
            int r = i / (D / 4), p = i - r * (D / 4);
            uint2 vh = ((const uint2*)Xh)[(size_t)(xb + r) * (D / 4) + p];
            *(uint2*)(sXh + r * QS + p * 4) = vh;
        }
        #pragma unroll
        for (int i = wtid; i < 32 * 16; i += 256) {
            int n = i >> 4, p = i & 15;
            uint2 vh = ((const uint2*)Lth)[(size_t)n * (N / 4) + xb / 4 + p];
            uint2 vl = ((const uint2*)Ltl)[(size_t)n * (N / 4) + xb / 4 + p];
            *(uint2*)(sLh + n * 72 + p * 4) = vh;
            *(uint2*)(sLl + n * 72 + p * 4) = vl;
        }
        if (wtid < 64) sXn[wtid] = Xn[xb + wtid];
        __syncthreads();

        // ---- phase 1: D1[16q x 64x] = (Qh + Ql) . Xh^T  (2 MMAs) ----
        float c1[8][4];
        #pragma unroll
        for (int i = 0; i < 8; i++)
            #pragma unroll
            for (int j = 0; j < 4; j++) c1[i][j] = 0.f;

        #pragma unroll
        for (int kt = 0; kt < D / 16; kt++) {
            const int k0 = kt * 16 + 2 * t;
            uint32_t ah[4], al[4];
            ah[0] = ldsw(sQh + (wq0 + qr) * QS + k0);
            ah[1] = ldsw(sQh + (wq0 + qr + 8) * QS + k0);
            ah[2] = ldsw(sQh + (wq0 + qr) * QS + k0 + 8);
            ah[3] = ldsw(sQh + (wq0 + qr + 8) * QS + k0 + 8);
            al[0] = ldsw(sQl + (wq0 + qr) * QS + k0);
            al[1] = ldsw(sQl + (wq0 + qr + 8) * QS + k0);
            al[2] = ldsw(sQl + (wq0 + qr) * QS + k0 + 8);
            al[3] = ldsw(sQl + (wq0 + qr + 8) * QS + k0 + 8);
            #pragma unroll
            for (int nt = 0; nt < 8; nt++) {
                const int xr = nt * 8 + qr;
                uint32_t bh0 = ldsw(sXh + xr * QS + k0);
                uint32_t bh1 = ldsw(sXh + xr * QS + k0 + 8);
                mma_f16(c1[nt], ah, bh0, bh1);
                mma_f16(c1[nt], al, bh0, bh1);
            }
        }

        // ---- epilogue: exp -> P fragments (C m16n8 -> A m16k16 repack) ----
        uint32_t Ph[4][4], Pl[4][4];
        #pragma unroll
        for (int kt2 = 0; kt2 < 4; kt2++) {
            #pragma unroll
            for (int s = 0; s < 2; s++) {
                const int nt = 2 * kt2 + s;
                const int x0 = nt * 8 + 2 * t;
                float xna = sXn[x0], xnb = sXn[x0 + 1];
                float p0 = __expf(-0.0078125f * fmaxf(qn0 + xna - 2.f * c1[nt][0], 0.f));
                float p1 = __expf(-0.0078125f * fmaxf(qn0 + xnb - 2.f * c1[nt][1], 0.f));
                float p2 = __expf(-0.0078125f * fmaxf(qn1 + xna - 2.f * c1[nt][2], 0.f));
                float p3 = __expf(-0.0078125f * fmaxf(qn1 + xnb - 2.f * c1[nt][3], 0.f));
                uint32_t w0 = packhf(p0, p1);
                uint32_t w1 = packhf(p2, p3);
                float2 f0 = up2(w0), f1 = up2(w1);
                Ph[kt2][2 * s]     = w0;
                Ph[kt2][2 * s + 1] = w1;
                Pl[kt2][2 * s]     = packhf(p0 - f0.x, p1 - f0.y);
                Pl[kt2][2 * s + 1] = packhf(p2 - f1.x, p3 - f1.y);
            }
        }

        // ---- phase 2: z += P . Lambda^T (3 MMAs) ----
        #pragma unroll
        for (int kt2 = 0; kt2 < 4; kt2++) {
            const int k0 = kt2 * 16 + 2 * t;
            #pragma unroll
            for (int nt = 0; nt < 4; nt++) {
                const int nc = nt * 8 + qr;
                uint32_t bh0 = ldsw(sLh + nc * 72 + k0);
                uint32_t bh1 = ldsw(sLh + nc * 72 + k0 + 8);
                uint32_t bl0 = ldsw(sLl + nc * 72 + k0);
                uint32_t bl1 = ldsw(sLl + nc * 72 + k0 + 8);
                mma_f16(zc[nt], Ph[kt2], bh0, bh1);
                mma_f16(zc[nt], Ph[kt2], bl0, bl1);
                mma_f16(zc[nt], Pl[kt2], bh0, bh1);
            }
        }
        __syncthreads();
    }

    // ---- combine the two x-half partial sums ----
    const int row0 = wq0 + qr;
    if (g == 1) {
        #pragma unroll
        for (int nt = 0; nt < 4; nt++) {
            const int col = nt * 8 + 2 * t;
            sRed[row0 * 33 + col]           = zc[nt][0];
            sRed[row0 * 33 + col + 1]       = zc[nt][1];
            sRed[(row0 + 8) * 33 + col]     = zc[nt][2];
            sRed[(row0 + 8) * 33 + col + 1] = zc[nt][3];
        }
    }
    __syncthreads();
    if (g == 0) {
        #pragma unroll
        for (int nt = 0; nt < 4; nt++) {
            const int col = nt * 8 + 2 * t;
            float v0 = zc[nt][0] + sRed[row0 * 33 + col];
            float v1 = zc[nt][1] + sRed[row0 * 33 + col + 1];
            float v2 = zc[nt][2] + sRed[(row0 + 8) * 33 + col];
            float v3 = zc[nt][3] + sRed[(row0 + 8) * 33 + col + 1];
            Zg[(size_t)(qb + row0) * 32 + col]           = v0;
            Zg[(size_t)(qb + row0) * 32 + col + 1]       = v1;
            Zg[(size_t)(qb + row0 + 8) * 32 + col]       = v2;
            Zg[(size_t)(qb + row0 + 8) * 32 + col + 1]   = v3;
        }
    }
}

// D=96: (2*128*104 + 2*64*104 + 2*2*32*72) half + 2*64 f32 = 98816 B
#define FUSED_SMEM 99328

__global__ __launch_bounds__(512, 1) void fusedtc_kernel() {
    extern __shared__ char sm[];
    int task = blockIdx.x >> 6;
    int qb   = (blockIdx.x & 63) * 128;
    if (task == 0)
        ftc<64>(sm, g_Xmh, g_xqm, g_Lth0, g_Ltl0, g_Xnm, g_qnm, g_zm, qb);
    else
        ftc<96>(sm, g_Xvh, g_xqv, g_Lth1, g_Ltl1, g_Xnv, g_qnv, g_zv, qb);
}

// -------------------- combine ----------------------------------------------
__global__ void combine_kernel(const float* __restrict__ y_mean,
                               const float* __restrict__ y_var,
                               float* __restrict__ out) {
    int i = blockIdx.x * blockDim.x + threadIdx.x;
    if (i < N * 32)
        out[i] = (y_mean[i] + g_zm[i]) + (y_var[i] + g_zv[i]);
}

// -------------------- launch ------------------------------------------------
extern "C" void kernel_launch(void* const* d_in, const int* in_sizes, int n_in,
                              void* d_out, int out_size) {
    const float* x_mu   = (const float*)d_in[0];
    const float* y_eta  = (const float*)d_in[1];
    const float* y_mean = (const float*)d_in[2];
    const float* y_var  = (const float*)d_in[3];
    const float* X_mean = (const float*)d_in[4];
    const float* X_var  = (const float*)d_in[5];
    const float* Z_mean = (const float*)d_in[6];
    const float* Z_var  = (const float*)d_in[7];
    const float* kMi    = (const float*)d_in[8];
    const float* kVi    = (const float*)d_in[9];
    float* out = (float*)d_out;

    cudaFuncSetAttribute(fusedtc_kernel,
                         cudaFuncAttributeMaxDynamicSharedMemorySize, FUSED_SMEM);

    prep_q_kernel<<<(N * 32 + 255) / 256, 256>>>(x_mu, y_eta, y_mean, y_var);
    prep_X_kernel<<<(N * 32 + 255) / 256, 256>>>(X_mean, X_var);
    zsplit_kernel<<<(2 * 32 * N + 255) / 256, 256>>>(Z_mean, Z_var);
    lambda_hmma_kernel<<<dim3(64, 2, 2), 256>>>(kMi, kVi);
    lsplit_kernel<<<(2 * 32 * N + 255) / 256, 256>>>();
    fusedtc_kernel<<<128, 512, FUSED_SMEM>>>();
    combine_kernel<<<(N * 32 + 255) / 256, 256>>>(y_mean, y_var, out);
}

// round 9
// speedup vs baseline: 10.9038x; 1.1308x over previous
#include <cuda_runtime.h>
#include <cuda_fp16.h>
#include <cstdint>

#define N 8192

// -------------------- device scratch ---------------------------------------
__device__ float g_xqm[N * 64];
__device__ float g_xqv[N * 96];
__device__ float g_qnm[N], g_qnv[N], g_Xnm[N], g_Xnv[N];
__device__ float g_LpA0[N * 32], g_LpB0[N * 32];   // Lambda partials (k-halves)
__device__ float g_LpA1[N * 32], g_LpB1[N * 32];
__device__ float g_zm[N * 32], g_zv[N * 32];
__device__ __align__(16) __half g_Xmh[N * 64];          // X hi (phase1 hi-only)
__device__ __align__(16) __half g_Xvh[N * 96];
__device__ __align__(16) __half g_Lth0[32 * N], g_Ltl0[32 * N];
__device__ __align__(16) __half g_Lth1[32 * N], g_Ltl1[32 * N];
__device__ __align__(16) __half g_Zth0[32 * N], g_Ztl0[32 * N];
__device__ __align__(16) __half g_Zth1[32 * N], g_Ztl1[32 * N];

// -------------------- mma helpers (sm_80+ HMMA fp16) ------------------------
__device__ __forceinline__ void mma_f16(float c[4], const uint32_t a[4],
                                        uint32_t b0, uint32_t b1) {
    asm volatile(
        "mma.sync.aligned.m16n8k16.row.col.f32.f16.f16.f32 "
        "{%0,%1,%2,%3}, {%4,%5,%6,%7}, {%8,%9}, {%0,%1,%2,%3};"
        : "+f"(c[0]), "+f"(c[1]), "+f"(c[2]), "+f"(c[3])
        : "r"(a[0]), "r"(a[1]), "r"(a[2]), "r"(a[3]), "r"(b0), "r"(b1));
}
__device__ __forceinline__ uint32_t packhf(float lo, float hi) {
    uint32_t r;
    asm("cvt.rn.f16x2.f32 %0, %1, %2;" : "=r"(r) : "f"(hi), "f"(lo));
    return r;
}
__device__ __forceinline__ float2 up2(uint32_t w) {
    __half2 h = *reinterpret_cast<__half2*>(&w);
    return __half22float2(h);
}
__device__ __forceinline__ uint32_t ldsw(const __half* p) {
    return *(const uint32_t*)p;
}

// -------------------- prep kernels ------------------------------------------
__global__ void prep_q_kernel(const float* __restrict__ x_mu,
                              const float* __restrict__ y_eta,
                              const float* __restrict__ y_mean,
                              const float* __restrict__ y_var) {
    int q = (blockIdx.x * blockDim.x + threadIdx.x) >> 5;
    int lane = threadIdx.x & 31;
    if (q >= N) return;
    float a = x_mu[q * 32 + lane];
    float m = y_mean[q * 32 + lane] + y_var[q * 32 + lane];
    float e = 0.01f * y_eta[(N - 1 - q) * 32 + lane];
    g_xqm[q * 64 + lane] = a;       g_xqm[q * 64 + 32 + lane] = m;
    g_xqv[q * 96 + lane] = a;       g_xqv[q * 96 + 32 + lane] = e;
    g_xqv[q * 96 + 64 + lane] = m;
    float nm = a * a + m * m, nv = nm + e * e;
    #pragma unroll
    for (int o = 16; o; o >>= 1) {
        nm += __shfl_xor_sync(0xffffffffu, nm, o);
        nv += __shfl_xor_sync(0xffffffffu, nv, o);
    }
    if (lane == 0) { g_qnm[q] = nm; g_qnv[q] = nv; }
}

__global__ void prep_X_kernel(const float* __restrict__ Xm,
                              const float* __restrict__ Xv) {
    int i = (blockIdx.x * blockDim.x + threadIdx.x) >> 5;
    int lane = threadIdx.x & 31;
    if (i >= N) return;
    float nm = 0.f, nv = 0.f;
    #pragma unroll
    for (int c = 0; c < 64; c += 32) {
        float v = Xm[(size_t)i * 64 + c + lane];
        nm += v * v;
        g_Xmh[(size_t)i * 64 + c + lane] = __float2half_rn(v);
    }
    #pragma unroll
    for (int c = 0; c < 96; c += 32) {
        float v = Xv[(size_t)i * 96 + c + lane];
        nv += v * v;
        g_Xvh[(size_t)i * 96 + c + lane] = __float2half_rn(v);
    }
    #pragma unroll
    for (int o = 16; o; o >>= 1) {
        nm += __shfl_xor_sync(0xffffffffu, nm, o);
        nv += __shfl_xor_sync(0xffffffffu, nv, o);
    }
    if (lane == 0) { g_Xnm[i] = nm; g_Xnv[i] = nv; }
}

// Z -> transposed fp16 hi/lo [32][N]
__global__ void zsplit_kernel(const float* __restrict__ Z0,
                              const float* __restrict__ Z1) {
    int idx = blockIdx.x * blockDim.x + threadIdx.x;
    if (idx >= 2 * 32 * N) return;
    int t = idx >= 32 * N;
    int j = idx - t * 32 * N;
    int n = j / N, k = j - n * N;
    float v = (t ? Z1 : Z0)[(size_t)k * 32 + n];
    __half h = __float2half_rn(v);
    (t ? g_Zth1 : g_Zth0)[j] = h;
    (t ? g_Ztl1 : g_Ztl0)[j] = __float2half_rn(v - __half2float(h));
}

// -------------------- Lambda = kXX_inv @ Z on HMMA (fp16 hi/lo, 3-MMA) ------
__global__ __launch_bounds__(256, 2) void lambda_hmma_kernel(
    const float* __restrict__ A0, const float* __restrict__ A1) {
    const int task = blockIdx.y, kh = blockIdx.z;
    const float* A = task ? A1 : A0;
    const __half* Zh = task ? g_Zth1 : g_Zth0;
    const __half* Zl = task ? g_Ztl1 : g_Ztl0;
    float* Lp = task ? (kh ? g_LpB1 : g_LpA1) : (kh ? g_LpB0 : g_LpA0);

    __shared__ __align__(16) uint32_t sAh[128 * 36], sAl[128 * 36];
    __shared__ __align__(16) uint32_t sZh[32 * 36], sZl[32 * 36];

    const int tid = threadIdx.x, lane = tid & 31, w = tid >> 5;
    const int t = lane & 3, qr = lane >> 2;
    const int rb = blockIdx.x * 128;
    const int kb0 = kh * (N / 2);
    const int zn = (tid * 4) >> 5, zw4 = (tid * 4) & 31;

    float4 pa[8];
    uint4 pzh, pzl;
    #pragma unroll
    for (int it = 0; it < 8; it++) {
        int idx = tid + it * 256;
        int r = idx >> 4, c4 = idx & 15;
        pa[it] = *(const float4*)&A[(size_t)(rb + r) * N + kb0 + c4 * 4];
    }
    pzh = ((const uint4*)Zh)[(zn * (N / 2) + kb0 / 2 + zw4) >> 2];
    pzl = ((const uint4*)Zl)[(zn * (N / 2) + kb0 / 2 + zw4) >> 2];

    float zc[4][4];
    #pragma unroll
    for (int i = 0; i < 4; i++)
        #pragma unroll
        for (int j = 0; j < 4; j++) zc[i][j] = 0.f;

    for (int cb = 0; cb < 64; cb++) {
        __syncthreads();
        #pragma unroll
        for (int it = 0; it < 8; it++) {
            int idx = tid + it * 256;
            int r = idx >> 4, c4 = idx & 15;
            float4 v = pa[it];
            uint32_t h0 = packhf(v.x, v.y);
            uint32_t h1 = packhf(v.z, v.w);
            float2 f0 = up2(h0), f1 = up2(h1);
            *(uint2*)&sAh[r * 36 + c4 * 2] = make_uint2(h0, h1);
            *(uint2*)&sAl[r * 36 + c4 * 2] =
                make_uint2(packhf(v.x - f0.x, v.y - f0.y),
                           packhf(v.z - f1.x, v.w - f1.y));
        }
        *(uint4*)&sZh[zn * 36 + zw4] = pzh;
        *(uint4*)&sZl[zn * 36 + zw4] = pzl;
        __syncthreads();

        if (cb < 63) {
            const int ko = kb0 + (cb + 1) * 64;
            #pragma unroll
            for (int it = 0; it < 8; it++) {
                int idx = tid + it * 256;
                int r = idx >> 4, c4 = idx & 15;
                pa[it] = *(const float4*)&A[(size_t)(rb + r) * N + ko + c4 * 4];
            }
            pzh = ((const uint4*)Zh)[(zn * (N / 2) + ko / 2 + zw4) >> 2];
            pzl = ((const uint4*)Zl)[(zn * (N / 2) + ko / 2 + zw4) >> 2];
        }

        #pragma unroll
        for (int kt = 0; kt < 4; kt++) {
            const int kw = kt * 8 + t;
            uint32_t ah[4], al[4];
            ah[0] = sAh[(w * 16 + qr) * 36 + kw];
            ah[1] = sAh[(w * 16 + qr + 8) * 36 + kw];
            ah[2] = sAh[(w * 16 + qr) * 36 + kw + 4];
            ah[3] = sAh[(w * 16 + qr + 8) * 36 + kw + 4];
            al[0] = sAl[(w * 16 + qr) * 36 + kw];
            al[1] = sAl[(w * 16 + qr + 8) * 36 + kw];
            al[2] = sAl[(w * 16 + qr) * 36 + kw + 4];
            al[3] = sAl[(w * 16 + qr + 8) * 36 + kw + 4];
            #pragma unroll
            for (int nt = 0; nt < 4; nt++) {
                const int nc = nt * 8 + qr;
                uint32_t bh0 = sZh[nc * 36 + kw], bh1 = sZh[nc * 36 + kw + 4];
                uint32_t bl0 = sZl[nc * 36 + kw], bl1 = sZl[nc * 36 + kw + 4];
                mma_f16(zc[nt], ah, bh0, bh1);
                mma_f16(zc[nt], ah, bl0, bl1);
                mma_f16(zc[nt], al, bh0, bh1);
            }
        }
    }

    const int row0 = rb + w * 16 + qr;
    #pragma unroll
    for (int nt = 0; nt < 4; nt++) {
        const int col = nt * 8 + 2 * t;
        Lp[(size_t)row0 * 32 + col]           = zc[nt][0];
        Lp[(size_t)row0 * 32 + col + 1]       = zc[nt][1];
        Lp[(size_t)(row0 + 8) * 32 + col]     = zc[nt][2];
        Lp[(size_t)(row0 + 8) * 32 + col + 1] = zc[nt][3];
    }
}

// Lambda partial sums -> transposed fp16 hi/lo [32][N]
__global__ void lsplit_kernel() {
    int idx = blockIdx.x * blockDim.x + threadIdx.x;
    if (idx >= 2 * 32 * N) return;
    int t = idx >= 32 * N;
    int j = idx - t * 32 * N;
    int n = j / N, k = j - n * N;
    size_t src = (size_t)k * 32 + n;
    float v = (t ? g_LpA1 : g_LpA0)[src] + (t ? g_LpB1 : g_LpB0)[src];
    __half h = __float2half_rn(v);
    (t ? g_Lth1 : g_Lth0)[j] = h;
    (t ? g_Ltl1 : g_Ltl0)[j] = __float2half_rn(v - __half2float(h));
}

// -------------------- fused HMMA kernel (fp16; phase1 hi-only 1-MMA) --------
template <int D>
__device__ void ftc(char* smraw, const __half* Xh,
                    const float* Qg, const __half* Lth,
                    const __half* Ltl, const float* Xn,
                    const float* Qn, float* Zg, int qb) {
    constexpr int QS = D + 8;
    __half* sQh  = (__half*)smraw;
    __half* sXhB = sQh + 128 * QS;
    __half* sLhB = sXhB + 2 * 64 * QS;
    __half* sLlB = sLhB + 2 * 32 * 72;
    float* sXnB = (float*)(sLlB + 2 * 32 * 72);
    float* sRed = (float*)sXhB;            // reused after the chunk loop

    const int tid = threadIdx.x;
    const int g = tid >> 8, wtid = tid & 255;
    const int lane = tid & 31, w = wtid >> 5;
    const int t = lane & 3, qr = lane >> 2;
    const int wq0 = w * 16;
    __half* sXh = sXhB + g * 64 * QS;
    __half* sLh = sLhB + g * 32 * 72;
    __half* sLl = sLlB + g * 32 * 72;
    float* sXn = sXnB + g * 64;

    // Q -> SMEM fp16 hi (all 512 threads)
    for (int i = tid; i < 128 * D; i += 512) {
        int r = i / D, c = i - r * D;
        sQh[r * QS + c] = __float2half_rn(Qg[(size_t)(qb + r) * D + c]);
    }
    const float qn0 = Qn[qb + wq0 + qr];
    const float qn1 = Qn[qb + wq0 + qr + 8];

    float zc[4][4];
    #pragma unroll
    for (int i = 0; i < 4; i++)
        #pragma unroll
        for (int j = 0; j < 4; j++) zc[i][j] = 0.f;

    for (int it = 0; it < 64; it++) {
        const int xb = (2 * it + g) * 64;
        // ---- stage this group's chunk ----
        #pragma unroll
        for (int i = wtid; i < 64 * (D / 4); i += 256) {
            int r = i / (D / 4), p = i - r * (D / 4);
            uint2 vh = ((const uint2*)Xh)[(size_t)(xb + r) * (D / 4) + p];
            *(uint2*)(sXh + r * QS + p * 4) = vh;
        }
        #pragma unroll
        for (int i = wtid; i < 32 * 16; i += 256) {
            int n = i >> 4, p = i & 15;
            uint2 vh = ((const uint2*)Lth)[(size_t)n * (N / 4) + xb / 4 + p];
            uint2 vl = ((const uint2*)Ltl)[(size_t)n * (N / 4) + xb / 4 + p];
            *(uint2*)(sLh + n * 72 + p * 4) = vh;
            *(uint2*)(sLl + n * 72 + p * 4) = vl;
        }
        if (wtid < 64) sXn[wtid] = Xn[xb + wtid];
        __syncthreads();

        // ---- phase 1: D1[16q x 64x] = Qh . Xh^T  (1 MMA / tile) ----
        float c1[8][4];
        #pragma unroll
        for (int i = 0; i < 8; i++)
            #pragma unroll
            for (int j = 0; j < 4; j++) c1[i][j] = 0.f;

        #pragma unroll
        for (int kt = 0; kt < D / 16; kt++) {
            const int k0 = kt * 16 + 2 * t;
            uint32_t ah[4];
            ah[0] = ldsw(sQh + (wq0 + qr) * QS + k0);
            ah[1] = ldsw(sQh + (wq0 + qr + 8) * QS + k0);
            ah[2] = ldsw(sQh + (wq0 + qr) * QS + k0 + 8);
            ah[3] = ldsw(sQh + (wq0 + qr + 8) * QS + k0 + 8);
            #pragma unroll
            for (int nt = 0; nt < 8; nt++) {
                const int xr = nt * 8 + qr;
                uint32_t bh0 = ldsw(sXh + xr * QS + k0);
                uint32_t bh1 = ldsw(sXh + xr * QS + k0 + 8);
                mma_f16(c1[nt], ah, bh0, bh1);
            }
        }

        // ---- epilogue: exp -> P fragments (C m16n8 -> A m16k16 repack) ----
        uint32_t Ph[4][4], Pl[4][4];
        #pragma unroll
        for (int kt2 = 0; kt2 < 4; kt2++) {
            #pragma unroll
            for (int s = 0; s < 2; s++) {
                const int nt = 2 * kt2 + s;
                const int x0 = nt * 8 + 2 * t;
                float xna = sXn[x0], xnb = sXn[x0 + 1];
                float p0 = __expf(-0.0078125f * fmaxf(qn0 + xna - 2.f * c1[nt][0], 0.f));
                float p1 = __expf(-0.0078125f * fmaxf(qn0 + xnb - 2.f * c1[nt][1], 0.f));
                float p2 = __expf(-0.0078125f * fmaxf(qn1 + xna - 2.f * c1[nt][2], 0.f));
                float p3 = __expf(-0.0078125f * fmaxf(qn1 + xnb - 2.f * c1[nt][3], 0.f));
                uint32_t w0 = packhf(p0, p1);
                uint32_t w1 = packhf(p2, p3);
                float2 f0 = up2(w0), f1 = up2(w1);
                Ph[kt2][2 * s]     = w0;
                Ph[kt2][2 * s + 1] = w1;
                Pl[kt2][2 * s]     = packhf(p0 - f0.x, p1 - f0.y);
                Pl[kt2][2 * s + 1] = packhf(p2 - f1.x, p3 - f1.y);
            }
        }

        // ---- phase 2: z += P . Lambda^T (3 MMAs) ----
        #pragma unroll
        for (int kt2 = 0; kt2 < 4; kt2++) {
            const int k0 = kt2 * 16 + 2 * t;
            #pragma unroll
            for (int nt = 0; nt < 4; nt++) {
                const int nc = nt * 8 + qr;
                uint32_t bh0 = ldsw(sLh + nc * 72 + k0);
                uint32_t bh1 = ldsw(sLh + nc * 72 + k0 + 8);
                uint32_t bl0 = ldsw(sLl + nc * 72 + k0);
                uint32_t bl1 = ldsw(sLl + nc * 72 + k0 + 8);
                mma_f16(zc[nt], Ph[kt2], bh0, bh1);
                mma_f16(zc[nt], Ph[kt2], bl0, bl1);
                mma_f16(zc[nt], Pl[kt2], bh0, bh1);
            }
        }
        __syncthreads();
    }

    // ---- combine the two x-half partial sums ----
    const int row0 = wq0 + qr;
    if (g == 1) {
        #pragma unroll
        for (int nt = 0; nt < 4; nt++) {
            const int col = nt * 8 + 2 * t;
            sRed[row0 * 33 + col]           = zc[nt][0];
            sRed[row0 * 33 + col + 1]       = zc[nt][1];
            sRed[(row0 + 8) * 33 + col]     = zc[nt][2];
            sRed[(row0 + 8) * 33 + col + 1] = zc[nt][3];
        }
    }
    __syncthreads();
    if (g == 0) {
        #pragma unroll
        for (int nt = 0; nt < 4; nt++) {
            const int col = nt * 8 + 2 * t;
            float v0 = zc[nt][0] + sRed[row0 * 33 + col];
            float v1 = zc[nt][1] + sRed[row0 * 33 + col + 1];
            float v2 = zc[nt][2] + sRed[(row0 + 8) * 33 + col];
            float v3 = zc[nt][3] + sRed[(row0 + 8) * 33 + col + 1];
            Zg[(size_t)(qb + row0) * 32 + col]           = v0;
            Zg[(size_t)(qb + row0) * 32 + col + 1]       = v1;
            Zg[(size_t)(qb + row0 + 8) * 32 + col]       = v2;
            Zg[(size_t)(qb + row0 + 8) * 32 + col + 1]   = v3;
        }
    }
}

// D=96: (128*104 + 2*64*104 + 2*2*32*72) half + 2*64 f32 = 71680 + 512
#define FUSED_SMEM 72704

__global__ __launch_bounds__(512, 1) void fusedtc_kernel() {
    extern __shared__ char sm[];
    int task = blockIdx.x >> 6;
    int qb   = (blockIdx.x & 63) * 128;
    if (task == 0)
        ftc<64>(sm, g_Xmh, g_xqm, g_Lth0, g_Ltl0, g_Xnm, g_qnm, g_zm, qb);
    else
        ftc<96>(sm, g_Xvh, g_xqv, g_Lth1, g_Ltl1, g_Xnv, g_qnv, g_zv, qb);
}

// -------------------- combine ----------------------------------------------
__global__ void combine_kernel(const float* __restrict__ y_mean,
                               const float* __restrict__ y_var,
                               float* __restrict__ out) {
    int i = blockIdx.x * blockDim.x + threadIdx.x;
    if (i < N * 32)
        out[i] = (y_mean[i] + g_zm[i]) + (y_var[i] + g_zv[i]);
}

// -------------------- launch ------------------------------------------------
extern "C" void kernel_launch(void* const* d_in, const int* in_sizes, int n_in,
                              void* d_out, int out_size) {
    const float* x_mu   = (const float*)d_in[0];
    const float* y_eta  = (const float*)d_in[1];
    const float* y_mean = (const float*)d_in[2];
    const float* y_var  = (const float*)d_in[3];
    const float* X_mean = (const float*)d_in[4];
    const float* X_var  = (const float*)d_in[5];
    const float* Z_mean = (const float*)d_in[6];
    const float* Z_var  = (const float*)d_in[7];
    const float* kMi    = (const float*)d_in[8];
    const float* kVi    = (const float*)d_in[9];
    float* out = (float*)d_out;

    cudaFuncSetAttribute(fusedtc_kernel,
                         cudaFuncAttributeMaxDynamicSharedMemorySize, FUSED_SMEM);

    prep_q_kernel<<<(N * 32 + 255) / 256, 256>>>(x_mu, y_eta, y_mean, y_var);
    prep_X_kernel<<<(N * 32 + 255) / 256, 256>>>(X_mean, X_var);
    zsplit_kernel<<<(2 * 32 * N + 255) / 256, 256>>>(Z_mean, Z_var);
    lambda_hmma_kernel<<<dim3(64, 2, 2), 256>>>(kMi, kVi);
    lsplit_kernel<<<(2 * 32 * N + 255) / 256, 256>>>();
    fusedtc_kernel<<<128, 512, FUSED_SMEM>>>();
    combine_kernel<<<(N * 32 + 255) / 256, 256>>>(y_mean, y_var, out);
}